// round 14
// baseline (speedup 1.0000x reference)
#include <cuda_runtime.h>
#include <cuda_bf16.h>
#include <math.h>

typedef unsigned long long u64;
typedef unsigned int u32;
#define DEV __device__ __forceinline__

constexpr int B = 4, TH = 120, STEPS = 8, D_IN = 32, D_MODEL = 512;
constexpr int N_HEADS = 8, N_LAYERS = 4, D_FF = 2048, N_SUB = 5;
constexpr int T = 128;          // TH + STEPS
constexpr int M = 512;          // B * T
constexpr float LN_EPS = 1e-5f;
constexpr float NEGMIN = -3.402823466e38f;
constexpr float EMB_SCALE = 22.627416997969522f;   // sqrt(512)
constexpr float INV_SQRT_DH = 0.125f;              // 1/sqrt(64)
constexpr int ATTN_SMEM = (128 * 68 + 32 * 132) * 4;  // 51712 bytes

// gemmw smem (bf16 elements): tile 64x64, stride-40 rows, double-buffered
constexpr int AH_E = 0;            // A hi: 64 x 40
constexpr int AL_E = 2560;         // A lo
constexpr int WH_E = 5120;         // W hi: 64 x 40
constexpr int WL_E = 7680;         // W lo
constexpr int BUF_E = 10240;       // elements per buffer
constexpr int GW_SMEM = BUF_E * 2 * 2;  // 40960 bytes

// converted-weight offsets (elements)
constexpr int WSZ = 4 * 512 * 512;
constexpr int WSZ_FF = 4 * 2048 * 512;
constexpr int OQ = 0, OK_ = WSZ, OV = 2 * WSZ, OO = 3 * WSZ;
constexpr int O1 = 4 * WSZ, O2 = 4 * WSZ + WSZ_FF;
constexpr int WTOTAL = 4 * WSZ + 2 * WSZ_FF;

// -------- device scratch (no allocations allowed) --------
__device__ float g_buf[B][T][D_IN];
__device__ float g_h[M][D_MODEL];
__device__ float g_q[M][D_MODEL];
__device__ float g_k[M][D_MODEL];
__device__ float g_v[M][D_MODEL];
__device__ float g_part[4][M][D_MODEL];
__device__ float g_cur[B][D_IN];
__device__ float g_ffr[B][D_FF];
__device__ __nv_bfloat16 g_hh[M][D_MODEL], g_hl[M][D_MODEL];   // h split
__device__ __nv_bfloat16 g_ah[M][D_MODEL], g_al[M][D_MODEL];   // attn split
__device__ __nv_bfloat16 g_fh[M][D_FF], g_fl[M][D_FF];         // ffn1 split
__device__ __nv_bfloat16 g_wh[WTOTAL], g_wl[WTOTAL];           // weights split

// -------- helpers --------
DEV u64 pack2(float lo, float hi) {
    u64 r; asm("mov.b64 %0, {%1, %2};" : "=l"(r) : "f"(lo), "f"(hi)); return r;
}
DEV float2 unpack2(u64 v) {
    float2 r; asm("mov.b64 {%0, %1}, %2;" : "=f"(r.x), "=f"(r.y) : "l"(v)); return r;
}
DEV void fma2(u64& c, u64 a, u64 b) {
    asm("fma.rn.f32x2 %0, %1, %2, %0;" : "+l"(c) : "l"(a), "l"(b));
}
union F4U { float4 f; u64 u[2]; };
DEV float4 ldg4(const float* p) { return __ldg((const float4*)p); }

DEV float gelu_fast(float x) {
    float w = 1.5957691216057308f * (x + 0.044715f * x * x * x);
    float t = 1.0f - 2.0f / (__expf(w) + 1.0f);
    return 0.5f * x * (1.0f + t);
}

DEV u32 smem_u32(const void* p) {
    u32 a;
    asm("{ .reg .u64 t; cvta.to.shared.u64 t, %1; cvt.u32.u64 %0, t; }"
        : "=r"(a) : "l"(p));
    return a;
}

DEV void ldsm_x4(u32* r, u32 addr) {
    asm volatile("ldmatrix.sync.aligned.m8n8.x4.shared.b16 {%0,%1,%2,%3}, [%4];"
                 : "=r"(r[0]), "=r"(r[1]), "=r"(r[2]), "=r"(r[3]) : "r"(addr));
}
DEV void ldsm_x2(u32* r, u32 addr) {
    asm volatile("ldmatrix.sync.aligned.m8n8.x2.shared.b16 {%0,%1}, [%2];"
                 : "=r"(r[0]), "=r"(r[1]) : "r"(addr));
}
DEV void mma_bf16(float* c, const u32* a, const u32* b) {
    asm volatile(
        "mma.sync.aligned.m16n8k16.row.col.f32.bf16.bf16.f32 "
        "{%0,%1,%2,%3}, {%4,%5,%6,%7}, {%8,%9}, {%0,%1,%2,%3};"
        : "+f"(c[0]), "+f"(c[1]), "+f"(c[2]), "+f"(c[3])
        : "r"(a[0]), "r"(a[1]), "r"(a[2]), "r"(a[3]), "r"(b[0]), "r"(b[1]));
}

struct O6 { float* p[6]; };
struct P4 { const float* p[4]; };

// =============== buf init ===============
__global__ void init_buf_kernel(const float* __restrict__ history) {
    int b = blockIdx.x;
    for (int idx = threadIdx.x; idx < T * D_IN; idx += blockDim.x) {
        int t = idx >> 5, i = idx & 31;
        g_buf[b][t][i] = (t < TH) ? history[(b * TH + t) * D_IN + i] : 0.0f;
    }
}

// =============== weight split conversion (once per launch) ===============
__global__ void wconv_kernel(const float* __restrict__ Wq, const float* __restrict__ Wk,
                             const float* __restrict__ Wv, const float* __restrict__ Wo,
                             const float* __restrict__ W1, const float* __restrict__ W2) {
    int seg = blockIdx.y;
    const float* src;
    __nv_bfloat16 *hi, *lo;
    int n;
    if (seg == 0)      { src = Wq; hi = g_wh + OQ;  lo = g_wl + OQ;  n = WSZ; }
    else if (seg == 1) { src = Wk; hi = g_wh + OK_; lo = g_wl + OK_; n = WSZ; }
    else if (seg == 2) { src = Wv; hi = g_wh + OV;  lo = g_wl + OV;  n = WSZ; }
    else if (seg == 3) { src = Wo; hi = g_wh + OO;  lo = g_wl + OO;  n = WSZ; }
    else if (seg == 4) { src = W1; hi = g_wh + O1;  lo = g_wl + O1;  n = WSZ_FF; }
    else               { src = W2; hi = g_wh + O2;  lo = g_wl + O2;  n = WSZ_FF; }
    int np = n >> 1;
    int stride = gridDim.x * blockDim.x;
    for (int i = blockIdx.x * blockDim.x + threadIdx.x; i < np; i += stride) {
        float2 x = ((const float2*)src)[i];
        __nv_bfloat16 h0 = __float2bfloat16(x.x), h1 = __float2bfloat16(x.y);
        __nv_bfloat162 hp; hp.x = h0; hp.y = h1;
        ((__nv_bfloat162*)hi)[i] = hp;
        __nv_bfloat162 lp;
        lp.x = __float2bfloat16(x.x - __bfloat162float(h0));
        lp.y = __float2bfloat16(x.y - __bfloat162float(h1));
        ((__nv_bfloat162*)lo)[i] = lp;
    }
}

// =============== embedding + positional encoding (+ bf16 split out) ========
__global__ void embed_kernel(const float* __restrict__ Wemb,
                             const float* __restrict__ bemb) {
    int row = blockIdx.x;
    int t = row & (T - 1);
    int b = row >> 7;
    __shared__ float xs[D_IN];
    int tid = threadIdx.x;             // 128
    if (tid < D_IN) xs[tid] = g_buf[b][t][tid];
    __syncthreads();
#pragma unroll
    for (int c = 0; c < 4; c++) {
        int d = tid + c * 128;
        const float* w = Wemb + d * D_IN;
        float s = 0.0f;
#pragma unroll
        for (int i = 0; i < 32; i += 4) {
            float4 wv = ldg4(&w[i]);
            s += wv.x * xs[i] + wv.y * xs[i + 1] + wv.z * xs[i + 2] + wv.w * xs[i + 3];
        }
        s = (s + __ldg(&bemb[d])) * EMB_SCALE;
        int j2 = d & ~1;
        float ang = (float)t * expf((float)j2 * (-9.210340371976184f / 512.0f));
        s += (d & 1) ? cosf(ang) : sinf(ang);
        g_h[row][d] = s;
        __nv_bfloat16 hh = __float2bfloat16(s);
        g_hh[row][d] = hh;
        g_hl[row][d] = __float2bfloat16(s - __bfloat162float(hh));
    }
}

// =============== warp-MMA split-bf16 GEMM, tile 64x64 ==========
// Block 256 thr / 8 warps; warp tile 32x16 (2m x 4n warp grid).
// C = Ah*Wh + Ah*Wl + Al*Wh, fp32 accum. K staged in 32-chunks, double-buffer.
// z: mat = z/NSPLIT (W select), split = z%NSPLIT (K range + out buffer).
// EPI 0: fp32 store to outs.p[z].  EPI 1: gelu(c+bias) -> bf16 hi/lo to Oh/Ol.
template <int NSPLIT, int EPI>
__global__ void __launch_bounds__(256) gemmw_kernel(
    const __nv_bfloat16* __restrict__ Ah, const __nv_bfloat16* __restrict__ Al,
    const __nv_bfloat16* __restrict__ Wh0, const __nv_bfloat16* __restrict__ Wh1,
    const __nv_bfloat16* __restrict__ Wh2,
    const __nv_bfloat16* __restrict__ Wl0, const __nv_bfloat16* __restrict__ Wl1,
    const __nv_bfloat16* __restrict__ Wl2,
    O6 outs, __nv_bfloat16* __restrict__ Oh, __nv_bfloat16* __restrict__ Ol,
    const float* __restrict__ bias, int N, int Kfull, int KS) {
    extern __shared__ __nv_bfloat16 smw[];
    u32 smb = smem_u32(smw);
    int tid = threadIdx.x, wid = tid >> 5, lid = tid & 31;
    int z = blockIdx.z;
    int mat = z / NSPLIT, split = z - mat * NSPLIT;
    const __nv_bfloat16* Wh = mat == 0 ? Wh0 : (mat == 1 ? Wh1 : Wh2);
    const __nv_bfloat16* Wl = mat == 0 ? Wl0 : (mat == 1 ? Wl1 : Wl2);
    float* O = outs.p[z];
    int koff = split * KS;
    int m0 = blockIdx.y * 64, n0 = blockIdx.x * 64;
    int mwarp = (wid & 1) * 32, nwarp = (wid >> 1) * 16;

    float c[2][2][4];
#pragma unroll
    for (int mt = 0; mt < 2; mt++)
#pragma unroll
        for (int nt = 0; nt < 2; nt++)
#pragma unroll
            for (int i = 0; i < 4; i++) c[mt][nt][i] = 0.0f;

    // staging: A 64x32 (1 uint4/thread/array), W 64x32 (1 uint4/thread/array)
    int srow = tid >> 2, seg = tid & 3;
    long aoff = (long)(m0 + srow) * Kfull + koff + seg * 8;
    long woff = (long)(n0 + srow) * Kfull + koff + seg * 8;
    int sE = srow * 40 + seg * 8;

    uint4 rah, ral, rwh, rwl;
    rah = *(const uint4*)(Ah + aoff);
    ral = *(const uint4*)(Al + aoff);
    rwh = *(const uint4*)(Wh + woff);
    rwl = *(const uint4*)(Wl + woff);
    *(uint4*)&smw[AH_E + sE] = rah;
    *(uint4*)&smw[AL_E + sE] = ral;
    *(uint4*)&smw[WH_E + sE] = rwh;
    *(uint4*)&smw[WL_E + sE] = rwl;
    __syncthreads();

    // ldmatrix lane base offsets (elements)
    int aRowOff = (lid & 15) * 40 + (lid >> 4) * 8;      // + mt*16*40 + ks
    int bRowOff = (lid & 7) * 40 + ((lid >> 3) & 1) * 8; // + nt*8*40 + ks

    int nch = KS / 32;
    int buf = 0;
    for (int ch = 0; ch < nch; ch++) {
        bool more = (ch + 1) < nch;
        if (more) {
            long o2 = aoff + (ch + 1) * 32;
            long w2 = woff + (ch + 1) * 32;
            rah = *(const uint4*)(Ah + o2);
            ral = *(const uint4*)(Al + o2);
            rwh = *(const uint4*)(Wh + w2);
            rwl = *(const uint4*)(Wl + w2);
        }
        int bufE = buf * BUF_E;
#pragma unroll
        for (int ks = 0; ks < 32; ks += 16) {
            u32 ah[2][4], al[2][4], bh[2][2], bl[2][2];
#pragma unroll
            for (int mt = 0; mt < 2; mt++) {
                int eoff = bufE + (mwarp + mt * 16) * 40 + aRowOff + ks;
                ldsm_x4(ah[mt], smb + 2 * (AH_E + eoff));
                ldsm_x4(al[mt], smb + 2 * (AL_E + eoff));
            }
#pragma unroll
            for (int nt = 0; nt < 2; nt++) {
                int eoff = bufE + (nwarp + nt * 8) * 40 + bRowOff + ks;
                ldsm_x2(bh[nt], smb + 2 * (WH_E + eoff));
                ldsm_x2(bl[nt], smb + 2 * (WL_E + eoff));
            }
#pragma unroll
            for (int mt = 0; mt < 2; mt++)
#pragma unroll
                for (int nt = 0; nt < 2; nt++) {
                    mma_bf16(c[mt][nt], ah[mt], bh[nt]);
                    mma_bf16(c[mt][nt], ah[mt], bl[nt]);
                    mma_bf16(c[mt][nt], al[mt], bh[nt]);
                }
        }
        if (more) {
            int nbE = (buf ^ 1) * BUF_E;
            *(uint4*)&smw[nbE + AH_E + sE] = rah;
            *(uint4*)&smw[nbE + AL_E + sE] = ral;
            *(uint4*)&smw[nbE + WH_E + sE] = rwh;
            *(uint4*)&smw[nbE + WL_E + sE] = rwl;
        }
        __syncthreads();
        buf ^= 1;
    }

    // epilogue: c0,c1 -> (row, col..col+1); c2,c3 -> (row+8, ...)
    int r0 = m0 + mwarp + (lid >> 2);
    int cbase = n0 + nwarp + 2 * (lid & 3);
#pragma unroll
    for (int mt = 0; mt < 2; mt++) {
#pragma unroll
        for (int nt = 0; nt < 2; nt++) {
            int row = r0 + mt * 16;
            int col = cbase + nt * 8;
            float v0 = c[mt][nt][0], v1 = c[mt][nt][1];
            float v2 = c[mt][nt][2], v3 = c[mt][nt][3];
            if (EPI == 0) {
                float2 p01 = {v0, v1};
                float2 p23 = {v2, v3};
                *(float2*)&O[(long)row * N + col] = p01;
                *(float2*)&O[(long)(row + 8) * N + col] = p23;
            } else {
                float b0 = __ldg(&bias[col]), b1 = __ldg(&bias[col + 1]);
                v0 = gelu_fast(v0 + b0); v1 = gelu_fast(v1 + b1);
                v2 = gelu_fast(v2 + b0); v3 = gelu_fast(v3 + b1);
                __nv_bfloat16 h0 = __float2bfloat16(v0), h1 = __float2bfloat16(v1);
                __nv_bfloat16 h2 = __float2bfloat16(v2), h3 = __float2bfloat16(v3);
                __nv_bfloat162 hp0; hp0.x = h0; hp0.y = h1;
                __nv_bfloat162 hp1; hp1.x = h2; hp1.y = h3;
                *(__nv_bfloat162*)&Oh[(long)row * N + col] = hp0;
                *(__nv_bfloat162*)&Oh[(long)(row + 8) * N + col] = hp1;
                __nv_bfloat162 lp0, lp1;
                lp0.x = __float2bfloat16(v0 - __bfloat162float(h0));
                lp0.y = __float2bfloat16(v1 - __bfloat162float(h1));
                lp1.x = __float2bfloat16(v2 - __bfloat162float(h2));
                lp1.y = __float2bfloat16(v3 - __bfloat162float(h3));
                *(__nv_bfloat162*)&Ol[(long)row * N + col] = lp0;
                *(__nv_bfloat162*)&Ol[(long)(row + 8) * N + col] = lp1;
            }
        }
    }
}

// =============== fused LayerNorm (+ bf16 split out) =========
template <int NP, bool HB>
__global__ void ln_fuse_kernel(const float* __restrict__ X, P4 P,
                               const float* __restrict__ bias,
                               const float* __restrict__ gam,
                               const float* __restrict__ bet,
                               float* __restrict__ O) {
    int row = blockIdx.x * 4 + (threadIdx.x >> 5);
    int lane = threadIdx.x & 31;
    float4 x[4];
    float s = 0.0f;
#pragma unroll
    for (int i = 0; i < 4; i++) {
        int col = lane * 4 + i * 128;
        x[i] = ldg4(&X[row * 512 + col]);
#pragma unroll
        for (int j = 0; j < NP; j++) {
            float4 pv = ldg4(&P.p[j][row * 512 + col]);
            x[i].x += pv.x; x[i].y += pv.y; x[i].z += pv.z; x[i].w += pv.w;
        }
        if (HB) {
            float4 b4 = ldg4(&bias[col]);
            x[i].x += b4.x; x[i].y += b4.y; x[i].z += b4.z; x[i].w += b4.w;
        }
        s += x[i].x + x[i].y + x[i].z + x[i].w;
    }
#pragma unroll
    for (int o = 16; o; o >>= 1) s += __shfl_xor_sync(~0u, s, o);
    float mu = s * (1.0f / 512.0f);
    float v = 0.0f;
#pragma unroll
    for (int i = 0; i < 4; i++) {
        x[i].x -= mu; x[i].y -= mu; x[i].z -= mu; x[i].w -= mu;
        v += x[i].x * x[i].x + x[i].y * x[i].y + x[i].z * x[i].z + x[i].w * x[i].w;
    }
#pragma unroll
    for (int o = 16; o; o >>= 1) v += __shfl_xor_sync(~0u, v, o);
    float inv = 1.0f / sqrtf(v * (1.0f / 512.0f) + LN_EPS);
#pragma unroll
    for (int i = 0; i < 4; i++) {
        int col = lane * 4 + i * 128;
        float4 g4 = ldg4(&gam[col]);
        float4 b4 = ldg4(&bet[col]);
        float4 o4;
        o4.x = x[i].x * inv * g4.x + b4.x;
        o4.y = x[i].y * inv * g4.y + b4.y;
        o4.z = x[i].z * inv * g4.z + b4.z;
        o4.w = x[i].w * inv * g4.w + b4.w;
        *(float4*)&O[row * 512 + col] = o4;
        __nv_bfloat16 h0 = __float2bfloat16(o4.x), h1 = __float2bfloat16(o4.y);
        __nv_bfloat16 h2 = __float2bfloat16(o4.z), h3 = __float2bfloat16(o4.w);
        __nv_bfloat162 hp0; hp0.x = h0; hp0.y = h1;
        __nv_bfloat162 hp1; hp1.x = h2; hp1.y = h3;
        *(__nv_bfloat162*)&g_hh[row][col] = hp0;
        *(__nv_bfloat162*)&g_hh[row][col + 2] = hp1;
        __nv_bfloat162 lp0, lp1;
        lp0.x = __float2bfloat16(o4.x - __bfloat162float(h0));
        lp0.y = __float2bfloat16(o4.y - __bfloat162float(h1));
        lp1.x = __float2bfloat16(o4.z - __bfloat162float(h2));
        lp1.y = __float2bfloat16(o4.w - __bfloat162float(h3));
        *(__nv_bfloat162*)&g_hl[row][col] = lp0;
        *(__nv_bfloat162*)&g_hl[row][col + 2] = lp1;
    }
}

// =============== Attention (fp32 in, bf16 split out) =========
// mask: attend where key index > query index (anti-causal, faithful to source)
__global__ void __launch_bounds__(256) attn_kernel() {
    extern __shared__ float smf[];
    float (*Ks)[68] = (float(*)[68])smf;
    float (*Ps)[132] = (float(*)[132])(smf + 128 * 68);
    int tid = threadIdx.x;
    int qr = tid >> 3, kg = tid & 7;
    int bx = blockIdx.x;
    int b = bx >> 5, h = (bx >> 2) & 7, qt = bx & 3;
    int base = b * T, hc = h * 64;
    int qi = qt * 32 + qr;

    for (int i = tid; i < 2048; i += 256) {
        int r = i >> 4, c = i & 15;
        *(float4*)&Ks[r][c * 4] = ldg4(&g_k[base + r][hc + c * 4]);
    }
    F4U q[16];
#pragma unroll
    for (int c = 0; c < 16; c++) q[c].f = ldg4(&g_q[base + qi][hc + c * 4]);
    __syncthreads();

    float sreg[16];
    float mloc = NEGMIN;
#pragma unroll
    for (int t = 0; t < 16; t++) {
        int k = kg + 8 * t;
        u64 a0 = pack2(0.f, 0.f), a1 = a0, a2 = a0, a3 = a0;
#pragma unroll
        for (int c = 0; c < 16; c += 2) {
            F4U k0; k0.f = *(const float4*)&Ks[k][c * 4];
            F4U k1; k1.f = *(const float4*)&Ks[k][c * 4 + 4];
            fma2(a0, q[c].u[0], k0.u[0]);
            fma2(a1, q[c].u[1], k0.u[1]);
            fma2(a2, q[c + 1].u[0], k1.u[0]);
            fma2(a3, q[c + 1].u[1], k1.u[1]);
        }
        float2 p0 = unpack2(a0), p1 = unpack2(a1), p2 = unpack2(a2), p3 = unpack2(a3);
        float s = (p0.x + p0.y) + (p1.x + p1.y) + (p2.x + p2.y) + (p3.x + p3.y);
        s = (k > qi) ? s * INV_SQRT_DH : NEGMIN;
        sreg[t] = s;
        mloc = fmaxf(mloc, s);
    }
    mloc = fmaxf(mloc, __shfl_xor_sync(~0u, mloc, 1));
    mloc = fmaxf(mloc, __shfl_xor_sync(~0u, mloc, 2));
    mloc = fmaxf(mloc, __shfl_xor_sync(~0u, mloc, 4));
    float lsum = 0.0f;
#pragma unroll
    for (int t = 0; t < 16; t++) {
        float p = __expf(sreg[t] - mloc);
        Ps[qr][kg + 8 * t] = p;
        lsum += p;
    }
    lsum += __shfl_xor_sync(~0u, lsum, 1);
    lsum += __shfl_xor_sync(~0u, lsum, 2);
    lsum += __shfl_xor_sync(~0u, lsum, 4);
    float invl = 1.0f / lsum;

    __syncthreads();
    for (int i = tid; i < 2048; i += 256) {
        int r = i >> 4, c = i & 15;
        *(float4*)&Ks[r][c * 4] = ldg4(&g_v[base + r][hc + c * 4]);
    }
    __syncthreads();

    F4U o[2];
    o[0].u[0] = pack2(0.f, 0.f); o[0].u[1] = o[0].u[0];
    o[1].u[0] = o[0].u[0]; o[1].u[1] = o[0].u[0];
#pragma unroll 4
    for (int k = 0; k < 128; k++) {
        float p = Ps[qr][k];
        u64 p2 = pack2(p, p);
#pragma unroll
        for (int c = 0; c < 2; c++) {
            F4U v; v.f = *(const float4*)&Ks[k][kg * 4 + c * 32];
            fma2(o[c].u[0], p2, v.u[0]);
            fma2(o[c].u[1], p2, v.u[1]);
        }
    }
#pragma unroll
    for (int c = 0; c < 2; c++) {
        float r0 = o[c].f.x * invl, r1 = o[c].f.y * invl;
        float r2 = o[c].f.z * invl, r3 = o[c].f.w * invl;
        int colb = hc + kg * 4 + c * 32;
        __nv_bfloat16 h0 = __float2bfloat16(r0), h1 = __float2bfloat16(r1);
        __nv_bfloat16 h2 = __float2bfloat16(r2), h3 = __float2bfloat16(r3);
        __nv_bfloat162 hp0; hp0.x = h0; hp0.y = h1;
        __nv_bfloat162 hp1; hp1.x = h2; hp1.y = h3;
        *(__nv_bfloat162*)&g_ah[base + qi][colb] = hp0;
        *(__nv_bfloat162*)&g_ah[base + qi][colb + 2] = hp1;
        __nv_bfloat162 lp0, lp1;
        lp0.x = __float2bfloat16(r0 - __bfloat162float(h0));
        lp0.y = __float2bfloat16(r1 - __bfloat162float(h1));
        lp1.x = __float2bfloat16(r2 - __bfloat162float(h2));
        lp1.y = __float2bfloat16(r3 - __bfloat162float(h3));
        *(__nv_bfloat162*)&g_al[base + qi][colb] = lp0;
        *(__nv_bfloat162*)&g_al[base + qi][colb + 2] = lp1;
    }
}

// =============== refine head, stage A ===============
__global__ void __launch_bounds__(256) refineA_kernel(
    const float* __restrict__ Wemb, const float* __restrict__ bemb,
    const float* __restrict__ Wr1, const float* __restrict__ br1,
    int step, int first) {
    int b = blockIdx.x >> 4, part = blockIdx.x & 15;
    __shared__ float comb[1024];
    __shared__ float cur[32];
    int tid = threadIdx.x;
    int ptr = TH + step;
    if (tid < 32) cur[tid] = first ? g_buf[b][ptr - 1][tid] : g_cur[b][tid];
    __syncthreads();
    for (int d = tid; d < 512; d += 256) {
        const float* w = &Wemb[d * 32];
        float s = 0.0f;
#pragma unroll
        for (int i = 0; i < 32; i += 4) {
            float4 wv = ldg4(&w[i]);
            s += wv.x * cur[i] + wv.y * cur[i + 1] + wv.z * cur[i + 2] + wv.w * cur[i + 3];
        }
        comb[d] = (s + __ldg(&bemb[d])) * EMB_SCALE;
    }
    for (int d = tid; d < 512; d += 256) comb[512 + d] = g_h[b * T + ptr - 1][d];
    __syncthreads();

    int r = part * 128 + (tid >> 1);
    int half = tid & 1;
    const float* w = &Wr1[r * 1024 + half * 512];
    const float* cb = &comb[half * 512];
    u64 a0 = pack2(0.f, 0.f), a1 = pack2(0.f, 0.f);
    for (int i = 0; i < 512; i += 4) {
        F4U wv; wv.f = ldg4(&w[i]);
        F4U cv; cv.f = *(const float4*)&cb[i];
        fma2(a0, wv.u[0], cv.u[0]);
        fma2(a1, wv.u[1], cv.u[1]);
    }
    float2 x0 = unpack2(a0), x1 = unpack2(a1);
    float s = x0.x + x0.y + x1.x + x1.y;
    s += __shfl_xor_sync(~0u, s, 1);
    if (half == 0) g_ffr[b][r] = gelu_fast(s + __ldg(&br1[r]));
}

// =============== refine head, stage B ===============
__global__ void __launch_bounds__(256) refineB_kernel(
    const float* __restrict__ Wr2, const float* __restrict__ br2,
    float* __restrict__ out, int step, int first, int last) {
    int b = blockIdx.x;
    int tid = threadIdx.x;
    __shared__ float ff[2048];
    for (int i = tid; i < 2048; i += 256) ff[i] = g_ffr[b][i];
    __syncthreads();
    int i = tid >> 3, part = tid & 7;
    const float* w = &Wr2[i * 2048 + part * 256];
    const float* f = &ff[part * 256];
    u64 a0 = pack2(0.f, 0.f), a1 = pack2(0.f, 0.f);
    for (int j = 0; j < 256; j += 4) {
        F4U wv; wv.f = ldg4(&w[j]);
        F4U fv; fv.f = *(const float4*)&f[j];
        fma2(a0, wv.u[0], fv.u[0]);
        fma2(a1, wv.u[1], fv.u[1]);
    }
    float2 x0 = unpack2(a0), x1 = unpack2(a1);
    float s = x0.x + x0.y + x1.x + x1.y;
    s += __shfl_xor_sync(~0u, s, 1);
    s += __shfl_xor_sync(~0u, s, 2);
    s += __shfl_xor_sync(~0u, s, 4);
    if (part == 0) {
        int ptr = TH + step;
        float basev = first ? g_buf[b][ptr - 1][i] : g_cur[b][i];
        float nv = basev + s + __ldg(&br2[i]);
        g_cur[b][i] = nv;
        if (last) {
            g_buf[b][ptr][i] = nv;
            out[(b * STEPS + step) * D_IN + i] = nv;
        }
    }
}

// =============== host orchestration ===============
extern "C" void kernel_launch(void* const* d_in, const int* in_sizes, int n_in,
                              void* d_out, int out_size) {
    int o = (n_in >= 20) ? 1 : 0;   // "steps" scalar occupies index 1 if present
    const float* history = (const float*)d_in[0];
    const float* Wemb = (const float*)d_in[1 + o];
    const float* bemb = (const float*)d_in[2 + o];
    const float* Wq = (const float*)d_in[3 + o];
    const float* Wk = (const float*)d_in[4 + o];
    const float* Wv = (const float*)d_in[5 + o];
    const float* Wo = (const float*)d_in[6 + o];
    const float* ln1g = (const float*)d_in[7 + o];
    const float* ln1b = (const float*)d_in[8 + o];
    const float* W1 = (const float*)d_in[9 + o];
    const float* b1 = (const float*)d_in[10 + o];
    const float* W2 = (const float*)d_in[11 + o];
    const float* b2 = (const float*)d_in[12 + o];
    const float* ln2g = (const float*)d_in[13 + o];
    const float* ln2b = (const float*)d_in[14 + o];
    const float* Wr1 = (const float*)d_in[15 + o];
    const float* br1 = (const float*)d_in[16 + o];
    const float* Wr2 = (const float*)d_in[17 + o];
    const float* br2 = (const float*)d_in[18 + o];
    float* out = (float*)d_out;

    void* p;
    cudaGetSymbolAddress(&p, g_h);    float* ph = (float*)p;
    cudaGetSymbolAddress(&p, g_q);    float* pq = (float*)p;
    cudaGetSymbolAddress(&p, g_k);    float* pk = (float*)p;
    cudaGetSymbolAddress(&p, g_v);    float* pv = (float*)p;
    cudaGetSymbolAddress(&p, g_part); float* ppart = (float*)p;
    cudaGetSymbolAddress(&p, g_hh);   __nv_bfloat16* phh = (__nv_bfloat16*)p;
    cudaGetSymbolAddress(&p, g_hl);   __nv_bfloat16* phl = (__nv_bfloat16*)p;
    cudaGetSymbolAddress(&p, g_ah);   __nv_bfloat16* pah = (__nv_bfloat16*)p;
    cudaGetSymbolAddress(&p, g_al);   __nv_bfloat16* pal = (__nv_bfloat16*)p;
    cudaGetSymbolAddress(&p, g_fh);   __nv_bfloat16* pfh = (__nv_bfloat16*)p;
    cudaGetSymbolAddress(&p, g_fl);   __nv_bfloat16* pfl = (__nv_bfloat16*)p;
    cudaGetSymbolAddress(&p, g_wh);   __nv_bfloat16* pwh = (__nv_bfloat16*)p;
    cudaGetSymbolAddress(&p, g_wl);   __nv_bfloat16* pwl = (__nv_bfloat16*)p;
    float* pp0 = ppart;
    float* pp1 = ppart + M * D_MODEL;
    float* pp2 = ppart + 2 * M * D_MODEL;
    float* pp3 = ppart + 3 * M * D_MODEL;

    cudaFuncSetAttribute(attn_kernel, cudaFuncAttributeMaxDynamicSharedMemorySize,
                         ATTN_SMEM);
    cudaFuncSetAttribute(gemmw_kernel<1, 0>,
                         cudaFuncAttributeMaxDynamicSharedMemorySize, GW_SMEM);
    cudaFuncSetAttribute(gemmw_kernel<2, 0>,
                         cudaFuncAttributeMaxDynamicSharedMemorySize, GW_SMEM);
    cudaFuncSetAttribute(gemmw_kernel<1, 1>,
                         cudaFuncAttributeMaxDynamicSharedMemorySize, GW_SMEM);
    cudaFuncSetAttribute(gemmw_kernel<4, 0>,
                         cudaFuncAttributeMaxDynamicSharedMemorySize, GW_SMEM);

    O6 oqkv = {{pq, pk, pv, nullptr, nullptr, nullptr}};
    O6 owo = {{pp0, pp1, nullptr, nullptr, nullptr, nullptr}};
    O6 odummy = {{nullptr, nullptr, nullptr, nullptr, nullptr, nullptr}};
    O6 off2 = {{pp0, pp1, pp2, pp3, nullptr, nullptr}};
    P4 lp1 = {{pp0, pp1, nullptr, nullptr}};
    P4 lp2 = {{pp0, pp1, pp2, pp3}};

    init_buf_kernel<<<B, 256>>>(history);
    wconv_kernel<<<dim3(512, 6), 256>>>(Wq, Wk, Wv, Wo, W1, W2);

    for (int step = 0; step < STEPS; step++) {
        embed_kernel<<<M, 128>>>(Wemb, bemb);
        for (int l = 0; l < N_LAYERS; l++) {
            const __nv_bfloat16* wqh = pwh + OQ + l * 512 * 512;
            const __nv_bfloat16* wkh = pwh + OK_ + l * 512 * 512;
            const __nv_bfloat16* wvh = pwh + OV + l * 512 * 512;
            const __nv_bfloat16* woh = pwh + OO + l * 512 * 512;
            const __nv_bfloat16* w1h = pwh + O1 + l * 2048 * 512;
            const __nv_bfloat16* w2h = pwh + O2 + l * 512 * 2048;
            const __nv_bfloat16* wql = pwl + OQ + l * 512 * 512;
            const __nv_bfloat16* wkl = pwl + OK_ + l * 512 * 512;
            const __nv_bfloat16* wvl = pwl + OV + l * 512 * 512;
            const __nv_bfloat16* wol = pwl + OO + l * 512 * 512;
            const __nv_bfloat16* w1l = pwl + O1 + l * 2048 * 512;
            const __nv_bfloat16* w2l = pwl + O2 + l * 512 * 2048;

            // QKV: 3 mats, full K -> 192 blocks (64x64 tiles)
            gemmw_kernel<1, 0><<<dim3(8, 8, 3), 256, GW_SMEM>>>(
                phh, phl, wqh, wkh, wvh, wql, wkl, wvl,
                oqkv, nullptr, nullptr, nullptr, 512, 512, 512);
            attn_kernel<<<128, 256, ATTN_SMEM>>>();
            // Wo: split-K2 -> 128 blocks; partials into ln1
            gemmw_kernel<2, 0><<<dim3(8, 8, 2), 256, GW_SMEM>>>(
                pah, pal, woh, woh, woh, wol, wol, wol,
                owo, nullptr, nullptr, nullptr, 512, 512, 256);
            ln_fuse_kernel<2, false><<<128, 128>>>(
                ph, lp1, nullptr, ln1g + l * 512, ln1b + l * 512, ph);
            // FFN1: N=2048, gelu+bias -> bf16 split out; 256 blocks
            gemmw_kernel<1, 1><<<dim3(32, 8, 1), 256, GW_SMEM>>>(
                phh, phl, w1h, w1h, w1h, w1l, w1l, w1l,
                odummy, pfh, pfl, b1 + l * D_FF, 2048, 512, 512);
            // FFN2: K=2048 split-K4 -> 256 blocks; partials into ln2
            gemmw_kernel<4, 0><<<dim3(8, 8, 4), 256, GW_SMEM>>>(
                pfh, pfl, w2h, w2h, w2h, w2l, w2l, w2l,
                off2, nullptr, nullptr, nullptr, 512, 2048, 512);
            ln_fuse_kernel<4, true><<<128, 128>>>(
                ph, lp2, b2 + l * 512, ln2g + l * 512, ln2b + l * 512, ph);
        }
        for (int s = 0; s < N_SUB; s++) {
            refineA_kernel<<<64, 256>>>(Wemb, bemb, Wr1, br1, step, s == 0);
            refineB_kernel<<<4, 256>>>(Wr2, br2, out, step, s == 0, s == N_SUB - 1);
        }
    }
}

// round 15
// speedup vs baseline: 1.0768x; 1.0768x over previous
#include <cuda_runtime.h>
#include <cuda_bf16.h>
#include <math.h>

typedef unsigned long long u64;
typedef unsigned int u32;
#define DEV __device__ __forceinline__

constexpr int B = 4, TH = 120, STEPS = 8, D_IN = 32, D_MODEL = 512;
constexpr int N_HEADS = 8, N_LAYERS = 4, D_FF = 2048, N_SUB = 5;
constexpr int T = 128;          // TH + STEPS
constexpr int M = 512;          // B * T
constexpr float LN_EPS = 1e-5f;
constexpr float NEGMIN = -3.402823466e38f;
constexpr float EMB_SCALE = 22.627416997969522f;   // sqrt(512)
constexpr float INV_SQRT_DH = 0.125f;              // 1/sqrt(64)
constexpr int ATTN_SMEM = (128 * 68 + 32 * 132) * 4;  // 51712 bytes

// gemmw smem (bf16 elements): tile 64x64, stride-40 rows, 3-stage cp.async
constexpr int AH_E = 0;            // A hi: 64 x 40
constexpr int AL_E = 2560;         // A lo
constexpr int WH_E = 5120;         // W hi: 64 x 40
constexpr int WL_E = 7680;         // W lo
constexpr int BUF_E = 10240;       // elements per stage
constexpr int NSTAGE = 3;
constexpr int GW_SMEM = BUF_E * NSTAGE * 2;  // 61440 bytes

// converted-weight offsets (elements)
constexpr int WSZ = 4 * 512 * 512;
constexpr int WSZ_FF = 4 * 2048 * 512;
constexpr int OQ = 0, OK_ = WSZ, OV = 2 * WSZ, OO = 3 * WSZ;
constexpr int O1 = 4 * WSZ, O2 = 4 * WSZ + WSZ_FF;
constexpr int WTOTAL = 4 * WSZ + 2 * WSZ_FF;

// -------- device scratch (no allocations allowed) --------
__device__ float g_buf[B][T][D_IN];
__device__ float g_h[M][D_MODEL];
__device__ float g_q[M][D_MODEL];
__device__ float g_k[M][D_MODEL];
__device__ float g_v[M][D_MODEL];
__device__ float g_part[4][M][D_MODEL];
__device__ float g_cur[B][D_IN];
__device__ float g_ffr[B][D_FF];
__device__ __nv_bfloat16 g_hh[M][D_MODEL], g_hl[M][D_MODEL];   // h split
__device__ __nv_bfloat16 g_ah[M][D_MODEL], g_al[M][D_MODEL];   // attn split
__device__ __nv_bfloat16 g_fh[M][D_FF], g_fl[M][D_FF];         // ffn1 split
__device__ __nv_bfloat16 g_wh[WTOTAL], g_wl[WTOTAL];           // weights split

// -------- helpers --------
DEV u64 pack2(float lo, float hi) {
    u64 r; asm("mov.b64 %0, {%1, %2};" : "=l"(r) : "f"(lo), "f"(hi)); return r;
}
DEV float2 unpack2(u64 v) {
    float2 r; asm("mov.b64 {%0, %1}, %2;" : "=f"(r.x), "=f"(r.y) : "l"(v)); return r;
}
DEV void fma2(u64& c, u64 a, u64 b) {
    asm("fma.rn.f32x2 %0, %1, %2, %0;" : "+l"(c) : "l"(a), "l"(b));
}
union F4U { float4 f; u64 u[2]; };
DEV float4 ldg4(const float* p) { return __ldg((const float4*)p); }

DEV float gelu_fast(float x) {
    float w = 1.5957691216057308f * (x + 0.044715f * x * x * x);
    float t = 1.0f - 2.0f / (__expf(w) + 1.0f);
    return 0.5f * x * (1.0f + t);
}

DEV u32 smem_u32(const void* p) {
    u32 a;
    asm("{ .reg .u64 t; cvta.to.shared.u64 t, %1; cvt.u32.u64 %0, t; }"
        : "=r"(a) : "l"(p));
    return a;
}

DEV void ldsm_x4(u32* r, u32 addr) {
    asm volatile("ldmatrix.sync.aligned.m8n8.x4.shared.b16 {%0,%1,%2,%3}, [%4];"
                 : "=r"(r[0]), "=r"(r[1]), "=r"(r[2]), "=r"(r[3]) : "r"(addr));
}
DEV void mma_bf16(float* c, const u32* a, const u32* b) {
    asm volatile(
        "mma.sync.aligned.m16n8k16.row.col.f32.bf16.bf16.f32 "
        "{%0,%1,%2,%3}, {%4,%5,%6,%7}, {%8,%9}, {%0,%1,%2,%3};"
        : "+f"(c[0]), "+f"(c[1]), "+f"(c[2]), "+f"(c[3])
        : "r"(a[0]), "r"(a[1]), "r"(a[2]), "r"(a[3]), "r"(b[0]), "r"(b[1]));
}
DEV void cpasync16(u32 dst, const void* src) {
    asm volatile("cp.async.cg.shared.global [%0], [%1], 16;" :: "r"(dst), "l"(src));
}
#define CP_COMMIT() asm volatile("cp.async.commit_group;" ::: "memory")
#define CP_WAIT1() asm volatile("cp.async.wait_group 1;" ::: "memory")

struct O6 { float* p[6]; };
struct P4 { const float* p[4]; };

// =============== buf init ===============
__global__ void init_buf_kernel(const float* __restrict__ history) {
    int b = blockIdx.x;
    for (int idx = threadIdx.x; idx < T * D_IN; idx += blockDim.x) {
        int t = idx >> 5, i = idx & 31;
        g_buf[b][t][i] = (t < TH) ? history[(b * TH + t) * D_IN + i] : 0.0f;
    }
}

// =============== weight split conversion (once per launch) ===============
__global__ void wconv_kernel(const float* __restrict__ Wq, const float* __restrict__ Wk,
                             const float* __restrict__ Wv, const float* __restrict__ Wo,
                             const float* __restrict__ W1, const float* __restrict__ W2) {
    int seg = blockIdx.y;
    const float* src;
    __nv_bfloat16 *hi, *lo;
    int n;
    if (seg == 0)      { src = Wq; hi = g_wh + OQ;  lo = g_wl + OQ;  n = WSZ; }
    else if (seg == 1) { src = Wk; hi = g_wh + OK_; lo = g_wl + OK_; n = WSZ; }
    else if (seg == 2) { src = Wv; hi = g_wh + OV;  lo = g_wl + OV;  n = WSZ; }
    else if (seg == 3) { src = Wo; hi = g_wh + OO;  lo = g_wl + OO;  n = WSZ; }
    else if (seg == 4) { src = W1; hi = g_wh + O1;  lo = g_wl + O1;  n = WSZ_FF; }
    else               { src = W2; hi = g_wh + O2;  lo = g_wl + O2;  n = WSZ_FF; }
    int np = n >> 1;
    int stride = gridDim.x * blockDim.x;
    for (int i = blockIdx.x * blockDim.x + threadIdx.x; i < np; i += stride) {
        float2 x = ((const float2*)src)[i];
        __nv_bfloat16 h0 = __float2bfloat16(x.x), h1 = __float2bfloat16(x.y);
        __nv_bfloat162 hp; hp.x = h0; hp.y = h1;
        ((__nv_bfloat162*)hi)[i] = hp;
        __nv_bfloat162 lp;
        lp.x = __float2bfloat16(x.x - __bfloat162float(h0));
        lp.y = __float2bfloat16(x.y - __bfloat162float(h1));
        ((__nv_bfloat162*)lo)[i] = lp;
    }
}

// =============== embedding + positional encoding (+ bf16 split out) ========
__global__ void embed_kernel(const float* __restrict__ Wemb,
                             const float* __restrict__ bemb) {
    int row = blockIdx.x;
    int t = row & (T - 1);
    int b = row >> 7;
    __shared__ float xs[D_IN];
    int tid = threadIdx.x;             // 128
    if (tid < D_IN) xs[tid] = g_buf[b][t][tid];
    __syncthreads();
#pragma unroll
    for (int c = 0; c < 4; c++) {
        int d = tid + c * 128;
        const float* w = Wemb + d * D_IN;
        float s = 0.0f;
#pragma unroll
        for (int i = 0; i < 32; i += 4) {
            float4 wv = ldg4(&w[i]);
            s += wv.x * xs[i] + wv.y * xs[i + 1] + wv.z * xs[i + 2] + wv.w * xs[i + 3];
        }
        s = (s + __ldg(&bemb[d])) * EMB_SCALE;
        int j2 = d & ~1;
        float ang = (float)t * expf((float)j2 * (-9.210340371976184f / 512.0f));
        s += (d & 1) ? cosf(ang) : sinf(ang);
        g_h[row][d] = s;
        __nv_bfloat16 hh = __float2bfloat16(s);
        g_hh[row][d] = hh;
        g_hl[row][d] = __float2bfloat16(s - __bfloat162float(hh));
    }
}

// =============== warp-MMA split-bf16 GEMM, 64x64 tile, cp.async 3-stage =====
// Block 256 thr / 8 warps; warp tile 32x16 (2m x 4n warp grid).
// C = Ah*Wh + Ah*Wl + Al*Wh, fp32 accum. K chunks of 32, 3-stage pipeline.
// z: mat = z/NSPLIT (W select), split = z%NSPLIT (K range + out buffer).
// EPI 0: fp32 store to outs.p[z].  EPI 1: gelu(c+bias) -> bf16 hi/lo to Oh/Ol.
template <int NSPLIT, int EPI>
__global__ void __launch_bounds__(256) gemmw_kernel(
    const __nv_bfloat16* __restrict__ Ah, const __nv_bfloat16* __restrict__ Al,
    const __nv_bfloat16* __restrict__ Wh0, const __nv_bfloat16* __restrict__ Wh1,
    const __nv_bfloat16* __restrict__ Wh2,
    const __nv_bfloat16* __restrict__ Wl0, const __nv_bfloat16* __restrict__ Wl1,
    const __nv_bfloat16* __restrict__ Wl2,
    O6 outs, __nv_bfloat16* __restrict__ Oh, __nv_bfloat16* __restrict__ Ol,
    const float* __restrict__ bias, int N, int Kfull, int KS) {
    extern __shared__ __nv_bfloat16 smw[];
    u32 smb = smem_u32(smw);
    int tid = threadIdx.x, wid = tid >> 5, lid = tid & 31;
    int z = blockIdx.z;
    int mat = z / NSPLIT, split = z - mat * NSPLIT;
    const __nv_bfloat16* Wh = mat == 0 ? Wh0 : (mat == 1 ? Wh1 : Wh2);
    const __nv_bfloat16* Wl = mat == 0 ? Wl0 : (mat == 1 ? Wl1 : Wl2);
    float* O = outs.p[z];
    int koff = split * KS;
    int m0 = blockIdx.y * 64, n0 = blockIdx.x * 64;
    int mwarp = (wid & 1) * 32, nwarp = (wid >> 1) * 16;

    float c[2][2][4];
#pragma unroll
    for (int mt = 0; mt < 2; mt++)
#pragma unroll
        for (int nt = 0; nt < 2; nt++)
#pragma unroll
            for (int i = 0; i < 4; i++) c[mt][nt][i] = 0.0f;

    // staging: each thread copies one 16B slice per array per chunk
    int srow = tid >> 2, seg = tid & 3;
    const __nv_bfloat16* pa = Ah + (long)(m0 + srow) * Kfull + koff + seg * 8;
    const __nv_bfloat16* pal = Al + (long)(m0 + srow) * Kfull + koff + seg * 8;
    const __nv_bfloat16* pwh = Wh + (long)(n0 + srow) * Kfull + koff + seg * 8;
    const __nv_bfloat16* pwl = Wl + (long)(n0 + srow) * Kfull + koff + seg * 8;
    int sE = srow * 40 + seg * 8;

    int nch = KS / 32;
#define GW_ISSUE(ch, buf)                                                   \
    do {                                                                    \
        u32 bb = smb + 2u * ((buf) * BUF_E);                                \
        int kk2 = (ch) * 32;                                                \
        cpasync16(bb + 2u * (AH_E + sE), pa + kk2);                         \
        cpasync16(bb + 2u * (AL_E + sE), pal + kk2);                        \
        cpasync16(bb + 2u * (WH_E + sE), pwh + kk2);                        \
        cpasync16(bb + 2u * (WL_E + sE), pwl + kk2);                        \
    } while (0)

    GW_ISSUE(0, 0);
    CP_COMMIT();
    GW_ISSUE(1, 1);
    CP_COMMIT();

    // ldmatrix lane base offsets (elements)
    int aRowOff = (lid & 15) * 40 + (lid >> 4) * 8;              // A: + mt*16*40 + ks
    int bRowOff = ((lid & 7) + ((lid >> 4) & 1) * 8) * 40 + ((lid >> 3) & 1) * 8;

    int buf = 0;
    for (int ch = 0; ch < nch; ch++) {
        CP_WAIT1();
        __syncthreads();
        int lc = ch + NSTAGE - 1;
        if (lc < nch) {
            int lb = lc % NSTAGE;
            GW_ISSUE(lc, lb);
        }
        CP_COMMIT();

        int bufE = buf * BUF_E;
#pragma unroll
        for (int ks = 0; ks < 32; ks += 16) {
            u32 ah[2][4], al[2][4], bh[4], bl[4];
#pragma unroll
            for (int mt = 0; mt < 2; mt++) {
                int eoff = bufE + (mwarp + mt * 16) * 40 + aRowOff + ks;
                ldsm_x4(ah[mt], smb + 2 * (AH_E + eoff));
                ldsm_x4(al[mt], smb + 2 * (AL_E + eoff));
            }
            {
                int eoff = bufE + nwarp * 40 + bRowOff + ks;
                ldsm_x4(bh, smb + 2 * (WH_E + eoff));
                ldsm_x4(bl, smb + 2 * (WL_E + eoff));
            }
#pragma unroll
            for (int mt = 0; mt < 2; mt++)
#pragma unroll
                for (int nt = 0; nt < 2; nt++) {
                    mma_bf16(c[mt][nt], ah[mt], bh + nt * 2);
                    mma_bf16(c[mt][nt], ah[mt], bl + nt * 2);
                    mma_bf16(c[mt][nt], al[mt], bh + nt * 2);
                }
        }
        buf = (buf + 1) % NSTAGE;
    }
#undef GW_ISSUE

    // epilogue: c0,c1 -> (row, col..col+1); c2,c3 -> (row+8, ...)
    int r0 = m0 + mwarp + (lid >> 2);
    int cbase = n0 + nwarp + 2 * (lid & 3);
#pragma unroll
    for (int mt = 0; mt < 2; mt++) {
#pragma unroll
        for (int nt = 0; nt < 2; nt++) {
            int row = r0 + mt * 16;
            int col = cbase + nt * 8;
            float v0 = c[mt][nt][0], v1 = c[mt][nt][1];
            float v2 = c[mt][nt][2], v3 = c[mt][nt][3];
            if (EPI == 0) {
                float2 p01 = {v0, v1};
                float2 p23 = {v2, v3};
                *(float2*)&O[(long)row * N + col] = p01;
                *(float2*)&O[(long)(row + 8) * N + col] = p23;
            } else {
                float b0 = __ldg(&bias[col]), b1 = __ldg(&bias[col + 1]);
                v0 = gelu_fast(v0 + b0); v1 = gelu_fast(v1 + b1);
                v2 = gelu_fast(v2 + b0); v3 = gelu_fast(v3 + b1);
                __nv_bfloat16 h0 = __float2bfloat16(v0), h1 = __float2bfloat16(v1);
                __nv_bfloat16 h2 = __float2bfloat16(v2), h3 = __float2bfloat16(v3);
                __nv_bfloat162 hp0; hp0.x = h0; hp0.y = h1;
                __nv_bfloat162 hp1; hp1.x = h2; hp1.y = h3;
                *(__nv_bfloat162*)&Oh[(long)row * N + col] = hp0;
                *(__nv_bfloat162*)&Oh[(long)(row + 8) * N + col] = hp1;
                __nv_bfloat162 lp0, lp1;
                lp0.x = __float2bfloat16(v0 - __bfloat162float(h0));
                lp0.y = __float2bfloat16(v1 - __bfloat162float(h1));
                lp1.x = __float2bfloat16(v2 - __bfloat162float(h2));
                lp1.y = __float2bfloat16(v3 - __bfloat162float(h3));
                *(__nv_bfloat162*)&Ol[(long)row * N + col] = lp0;
                *(__nv_bfloat162*)&Ol[(long)(row + 8) * N + col] = lp1;
            }
        }
    }
}

// =============== fused LayerNorm (+ bf16 split out) =========
template <int NP, bool HB>
__global__ void ln_fuse_kernel(const float* __restrict__ X, P4 P,
                               const float* __restrict__ bias,
                               const float* __restrict__ gam,
                               const float* __restrict__ bet,
                               float* __restrict__ O) {
    int row = blockIdx.x * 4 + (threadIdx.x >> 5);
    int lane = threadIdx.x & 31;
    float4 x[4];
    float s = 0.0f;
#pragma unroll
    for (int i = 0; i < 4; i++) {
        int col = lane * 4 + i * 128;
        x[i] = ldg4(&X[row * 512 + col]);
#pragma unroll
        for (int j = 0; j < NP; j++) {
            float4 pv = ldg4(&P.p[j][row * 512 + col]);
            x[i].x += pv.x; x[i].y += pv.y; x[i].z += pv.z; x[i].w += pv.w;
        }
        if (HB) {
            float4 b4 = ldg4(&bias[col]);
            x[i].x += b4.x; x[i].y += b4.y; x[i].z += b4.z; x[i].w += b4.w;
        }
        s += x[i].x + x[i].y + x[i].z + x[i].w;
    }
#pragma unroll
    for (int o = 16; o; o >>= 1) s += __shfl_xor_sync(~0u, s, o);
    float mu = s * (1.0f / 512.0f);
    float v = 0.0f;
#pragma unroll
    for (int i = 0; i < 4; i++) {
        x[i].x -= mu; x[i].y -= mu; x[i].z -= mu; x[i].w -= mu;
        v += x[i].x * x[i].x + x[i].y * x[i].y + x[i].z * x[i].z + x[i].w * x[i].w;
    }
#pragma unroll
    for (int o = 16; o; o >>= 1) v += __shfl_xor_sync(~0u, v, o);
    float inv = 1.0f / sqrtf(v * (1.0f / 512.0f) + LN_EPS);
#pragma unroll
    for (int i = 0; i < 4; i++) {
        int col = lane * 4 + i * 128;
        float4 g4 = ldg4(&gam[col]);
        float4 b4 = ldg4(&bet[col]);
        float4 o4;
        o4.x = x[i].x * inv * g4.x + b4.x;
        o4.y = x[i].y * inv * g4.y + b4.y;
        o4.z = x[i].z * inv * g4.z + b4.z;
        o4.w = x[i].w * inv * g4.w + b4.w;
        *(float4*)&O[row * 512 + col] = o4;
        __nv_bfloat16 h0 = __float2bfloat16(o4.x), h1 = __float2bfloat16(o4.y);
        __nv_bfloat16 h2 = __float2bfloat16(o4.z), h3 = __float2bfloat16(o4.w);
        __nv_bfloat162 hp0; hp0.x = h0; hp0.y = h1;
        __nv_bfloat162 hp1; hp1.x = h2; hp1.y = h3;
        *(__nv_bfloat162*)&g_hh[row][col] = hp0;
        *(__nv_bfloat162*)&g_hh[row][col + 2] = hp1;
        __nv_bfloat162 lp0, lp1;
        lp0.x = __float2bfloat16(o4.x - __bfloat162float(h0));
        lp0.y = __float2bfloat16(o4.y - __bfloat162float(h1));
        lp1.x = __float2bfloat16(o4.z - __bfloat162float(h2));
        lp1.y = __float2bfloat16(o4.w - __bfloat162float(h3));
        *(__nv_bfloat162*)&g_hl[row][col] = lp0;
        *(__nv_bfloat162*)&g_hl[row][col + 2] = lp1;
    }
}

// =============== Attention (fp32 in, bf16 split out) =========
// mask: attend where key index > query index (anti-causal, faithful to source)
__global__ void __launch_bounds__(256) attn_kernel() {
    extern __shared__ float smf[];
    float (*Ks)[68] = (float(*)[68])smf;
    float (*Ps)[132] = (float(*)[132])(smf + 128 * 68);
    int tid = threadIdx.x;
    int qr = tid >> 3, kg = tid & 7;
    int bx = blockIdx.x;
    int b = bx >> 5, h = (bx >> 2) & 7, qt = bx & 3;
    int base = b * T, hc = h * 64;
    int qi = qt * 32 + qr;

    for (int i = tid; i < 2048; i += 256) {
        int r = i >> 4, c = i & 15;
        *(float4*)&Ks[r][c * 4] = ldg4(&g_k[base + r][hc + c * 4]);
    }
    F4U q[16];
#pragma unroll
    for (int c = 0; c < 16; c++) q[c].f = ldg4(&g_q[base + qi][hc + c * 4]);
    __syncthreads();

    float sreg[16];
    float mloc = NEGMIN;
#pragma unroll
    for (int t = 0; t < 16; t++) {
        int k = kg + 8 * t;
        u64 a0 = pack2(0.f, 0.f), a1 = a0, a2 = a0, a3 = a0;
#pragma unroll
        for (int c = 0; c < 16; c += 2) {
            F4U k0; k0.f = *(const float4*)&Ks[k][c * 4];
            F4U k1; k1.f = *(const float4*)&Ks[k][c * 4 + 4];
            fma2(a0, q[c].u[0], k0.u[0]);
            fma2(a1, q[c].u[1], k0.u[1]);
            fma2(a2, q[c + 1].u[0], k1.u[0]);
            fma2(a3, q[c + 1].u[1], k1.u[1]);
        }
        float2 p0 = unpack2(a0), p1 = unpack2(a1), p2 = unpack2(a2), p3 = unpack2(a3);
        float s = (p0.x + p0.y) + (p1.x + p1.y) + (p2.x + p2.y) + (p3.x + p3.y);
        s = (k > qi) ? s * INV_SQRT_DH : NEGMIN;
        sreg[t] = s;
        mloc = fmaxf(mloc, s);
    }
    mloc = fmaxf(mloc, __shfl_xor_sync(~0u, mloc, 1));
    mloc = fmaxf(mloc, __shfl_xor_sync(~0u, mloc, 2));
    mloc = fmaxf(mloc, __shfl_xor_sync(~0u, mloc, 4));
    float lsum = 0.0f;
#pragma unroll
    for (int t = 0; t < 16; t++) {
        float p = __expf(sreg[t] - mloc);
        Ps[qr][kg + 8 * t] = p;
        lsum += p;
    }
    lsum += __shfl_xor_sync(~0u, lsum, 1);
    lsum += __shfl_xor_sync(~0u, lsum, 2);
    lsum += __shfl_xor_sync(~0u, lsum, 4);
    float invl = 1.0f / lsum;

    __syncthreads();
    for (int i = tid; i < 2048; i += 256) {
        int r = i >> 4, c = i & 15;
        *(float4*)&Ks[r][c * 4] = ldg4(&g_v[base + r][hc + c * 4]);
    }
    __syncthreads();

    F4U o[2];
    o[0].u[0] = pack2(0.f, 0.f); o[0].u[1] = o[0].u[0];
    o[1].u[0] = o[0].u[0]; o[1].u[1] = o[0].u[0];
#pragma unroll 4
    for (int k = 0; k < 128; k++) {
        float p = Ps[qr][k];
        u64 p2 = pack2(p, p);
#pragma unroll
        for (int c = 0; c < 2; c++) {
            F4U v; v.f = *(const float4*)&Ks[k][kg * 4 + c * 32];
            fma2(o[c].u[0], p2, v.u[0]);
            fma2(o[c].u[1], p2, v.u[1]);
        }
    }
#pragma unroll
    for (int c = 0; c < 2; c++) {
        float r0 = o[c].f.x * invl, r1 = o[c].f.y * invl;
        float r2 = o[c].f.z * invl, r3 = o[c].f.w * invl;
        int colb = hc + kg * 4 + c * 32;
        __nv_bfloat16 h0 = __float2bfloat16(r0), h1 = __float2bfloat16(r1);
        __nv_bfloat16 h2 = __float2bfloat16(r2), h3 = __float2bfloat16(r3);
        __nv_bfloat162 hp0; hp0.x = h0; hp0.y = h1;
        __nv_bfloat162 hp1; hp1.x = h2; hp1.y = h3;
        *(__nv_bfloat162*)&g_ah[base + qi][colb] = hp0;
        *(__nv_bfloat162*)&g_ah[base + qi][colb + 2] = hp1;
        __nv_bfloat162 lp0, lp1;
        lp0.x = __float2bfloat16(r0 - __bfloat162float(h0));
        lp0.y = __float2bfloat16(r1 - __bfloat162float(h1));
        lp1.x = __float2bfloat16(r2 - __bfloat162float(h2));
        lp1.y = __float2bfloat16(r3 - __bfloat162float(h3));
        *(__nv_bfloat162*)&g_al[base + qi][colb] = lp0;
        *(__nv_bfloat162*)&g_al[base + qi][colb + 2] = lp1;
    }
}

// =============== refine head, stage A ===============
__global__ void __launch_bounds__(256) refineA_kernel(
    const float* __restrict__ Wemb, const float* __restrict__ bemb,
    const float* __restrict__ Wr1, const float* __restrict__ br1,
    int step, int first) {
    int b = blockIdx.x >> 4, part = blockIdx.x & 15;
    __shared__ float comb[1024];
    __shared__ float cur[32];
    int tid = threadIdx.x;
    int ptr = TH + step;
    if (tid < 32) cur[tid] = first ? g_buf[b][ptr - 1][tid] : g_cur[b][tid];
    __syncthreads();
    for (int d = tid; d < 512; d += 256) {
        const float* w = &Wemb[d * 32];
        float s = 0.0f;
#pragma unroll
        for (int i = 0; i < 32; i += 4) {
            float4 wv = ldg4(&w[i]);
            s += wv.x * cur[i] + wv.y * cur[i + 1] + wv.z * cur[i + 2] + wv.w * cur[i + 3];
        }
        comb[d] = (s + __ldg(&bemb[d])) * EMB_SCALE;
    }
    for (int d = tid; d < 512; d += 256) comb[512 + d] = g_h[b * T + ptr - 1][d];
    __syncthreads();

    int r = part * 128 + (tid >> 1);
    int half = tid & 1;
    const float* w = &Wr1[r * 1024 + half * 512];
    const float* cb = &comb[half * 512];
    u64 a0 = pack2(0.f, 0.f), a1 = pack2(0.f, 0.f);
    for (int i = 0; i < 512; i += 4) {
        F4U wv; wv.f = ldg4(&w[i]);
        F4U cv; cv.f = *(const float4*)&cb[i];
        fma2(a0, wv.u[0], cv.u[0]);
        fma2(a1, wv.u[1], cv.u[1]);
    }
    float2 x0 = unpack2(a0), x1 = unpack2(a1);
    float s = x0.x + x0.y + x1.x + x1.y;
    s += __shfl_xor_sync(~0u, s, 1);
    if (half == 0) g_ffr[b][r] = gelu_fast(s + __ldg(&br1[r]));
}

// =============== refine head, stage B ===============
__global__ void __launch_bounds__(256) refineB_kernel(
    const float* __restrict__ Wr2, const float* __restrict__ br2,
    float* __restrict__ out, int step, int first, int last) {
    int b = blockIdx.x;
    int tid = threadIdx.x;
    __shared__ float ff[2048];
    for (int i = tid; i < 2048; i += 256) ff[i] = g_ffr[b][i];
    __syncthreads();
    int i = tid >> 3, part = tid & 7;
    const float* w = &Wr2[i * 2048 + part * 256];
    const float* f = &ff[part * 256];
    u64 a0 = pack2(0.f, 0.f), a1 = pack2(0.f, 0.f);
    for (int j = 0; j < 256; j += 4) {
        F4U wv; wv.f = ldg4(&w[j]);
        F4U fv; fv.f = *(const float4*)&f[j];
        fma2(a0, wv.u[0], fv.u[0]);
        fma2(a1, wv.u[1], fv.u[1]);
    }
    float2 x0 = unpack2(a0), x1 = unpack2(a1);
    float s = x0.x + x0.y + x1.x + x1.y;
    s += __shfl_xor_sync(~0u, s, 1);
    s += __shfl_xor_sync(~0u, s, 2);
    s += __shfl_xor_sync(~0u, s, 4);
    if (part == 0) {
        int ptr = TH + step;
        float basev = first ? g_buf[b][ptr - 1][i] : g_cur[b][i];
        float nv = basev + s + __ldg(&br2[i]);
        g_cur[b][i] = nv;
        if (last) {
            g_buf[b][ptr][i] = nv;
            out[(b * STEPS + step) * D_IN + i] = nv;
        }
    }
}

// =============== host orchestration ===============
extern "C" void kernel_launch(void* const* d_in, const int* in_sizes, int n_in,
                              void* d_out, int out_size) {
    int o = (n_in >= 20) ? 1 : 0;   // "steps" scalar occupies index 1 if present
    const float* history = (const float*)d_in[0];
    const float* Wemb = (const float*)d_in[1 + o];
    const float* bemb = (const float*)d_in[2 + o];
    const float* Wq = (const float*)d_in[3 + o];
    const float* Wk = (const float*)d_in[4 + o];
    const float* Wv = (const float*)d_in[5 + o];
    const float* Wo = (const float*)d_in[6 + o];
    const float* ln1g = (const float*)d_in[7 + o];
    const float* ln1b = (const float*)d_in[8 + o];
    const float* W1 = (const float*)d_in[9 + o];
    const float* b1 = (const float*)d_in[10 + o];
    const float* W2 = (const float*)d_in[11 + o];
    const float* b2 = (const float*)d_in[12 + o];
    const float* ln2g = (const float*)d_in[13 + o];
    const float* ln2b = (const float*)d_in[14 + o];
    const float* Wr1 = (const float*)d_in[15 + o];
    const float* br1 = (const float*)d_in[16 + o];
    const float* Wr2 = (const float*)d_in[17 + o];
    const float* br2 = (const float*)d_in[18 + o];
    float* out = (float*)d_out;

    void* p;
    cudaGetSymbolAddress(&p, g_h);    float* ph = (float*)p;
    cudaGetSymbolAddress(&p, g_q);    float* pq = (float*)p;
    cudaGetSymbolAddress(&p, g_k);    float* pk = (float*)p;
    cudaGetSymbolAddress(&p, g_v);    float* pv = (float*)p;
    cudaGetSymbolAddress(&p, g_part); float* ppart = (float*)p;
    cudaGetSymbolAddress(&p, g_hh);   __nv_bfloat16* phh = (__nv_bfloat16*)p;
    cudaGetSymbolAddress(&p, g_hl);   __nv_bfloat16* phl = (__nv_bfloat16*)p;
    cudaGetSymbolAddress(&p, g_ah);   __nv_bfloat16* pah = (__nv_bfloat16*)p;
    cudaGetSymbolAddress(&p, g_al);   __nv_bfloat16* pal = (__nv_bfloat16*)p;
    cudaGetSymbolAddress(&p, g_fh);   __nv_bfloat16* pfh = (__nv_bfloat16*)p;
    cudaGetSymbolAddress(&p, g_fl);   __nv_bfloat16* pfl = (__nv_bfloat16*)p;
    cudaGetSymbolAddress(&p, g_wh);   __nv_bfloat16* pwh = (__nv_bfloat16*)p;
    cudaGetSymbolAddress(&p, g_wl);   __nv_bfloat16* pwl = (__nv_bfloat16*)p;
    float* pp0 = ppart;
    float* pp1 = ppart + M * D_MODEL;
    float* pp2 = ppart + 2 * M * D_MODEL;
    float* pp3 = ppart + 3 * M * D_MODEL;

    cudaFuncSetAttribute(attn_kernel, cudaFuncAttributeMaxDynamicSharedMemorySize,
                         ATTN_SMEM);
    cudaFuncSetAttribute(gemmw_kernel<1, 0>,
                         cudaFuncAttributeMaxDynamicSharedMemorySize, GW_SMEM);
    cudaFuncSetAttribute(gemmw_kernel<2, 0>,
                         cudaFuncAttributeMaxDynamicSharedMemorySize, GW_SMEM);
    cudaFuncSetAttribute(gemmw_kernel<1, 1>,
                         cudaFuncAttributeMaxDynamicSharedMemorySize, GW_SMEM);
    cudaFuncSetAttribute(gemmw_kernel<4, 0>,
                         cudaFuncAttributeMaxDynamicSharedMemorySize, GW_SMEM);

    O6 oqkv = {{pq, pk, pv, nullptr, nullptr, nullptr}};
    O6 owo = {{pp0, pp1, nullptr, nullptr, nullptr, nullptr}};
    O6 odummy = {{nullptr, nullptr, nullptr, nullptr, nullptr, nullptr}};
    O6 off2 = {{pp0, pp1, pp2, pp3, nullptr, nullptr}};
    P4 lp1 = {{pp0, pp1, nullptr, nullptr}};
    P4 lp2 = {{pp0, pp1, pp2, pp3}};

    init_buf_kernel<<<B, 256>>>(history);
    wconv_kernel<<<dim3(512, 6), 256>>>(Wq, Wk, Wv, Wo, W1, W2);

    for (int step = 0; step < STEPS; step++) {
        embed_kernel<<<M, 128>>>(Wemb, bemb);
        for (int l = 0; l < N_LAYERS; l++) {
            const __nv_bfloat16* wqh = pwh + OQ + l * 512 * 512;
            const __nv_bfloat16* wkh = pwh + OK_ + l * 512 * 512;
            const __nv_bfloat16* wvh = pwh + OV + l * 512 * 512;
            const __nv_bfloat16* woh = pwh + OO + l * 512 * 512;
            const __nv_bfloat16* w1h = pwh + O1 + l * 2048 * 512;
            const __nv_bfloat16* w2h = pwh + O2 + l * 512 * 2048;
            const __nv_bfloat16* wql = pwl + OQ + l * 512 * 512;
            const __nv_bfloat16* wkl = pwl + OK_ + l * 512 * 512;
            const __nv_bfloat16* wvl = pwl + OV + l * 512 * 512;
            const __nv_bfloat16* wol = pwl + OO + l * 512 * 512;
            const __nv_bfloat16* w1l = pwl + O1 + l * 2048 * 512;
            const __nv_bfloat16* w2l = pwl + O2 + l * 512 * 2048;

            // QKV: 3 mats, full K -> 192 blocks (64x64 tiles)
            gemmw_kernel<1, 0><<<dim3(8, 8, 3), 256, GW_SMEM>>>(
                phh, phl, wqh, wkh, wvh, wql, wkl, wvl,
                oqkv, nullptr, nullptr, nullptr, 512, 512, 512);
            attn_kernel<<<128, 256, ATTN_SMEM>>>();
            // Wo: split-K2 -> 128 blocks; partials into ln1
            gemmw_kernel<2, 0><<<dim3(8, 8, 2), 256, GW_SMEM>>>(
                pah, pal, woh, woh, woh, wol, wol, wol,
                owo, nullptr, nullptr, nullptr, 512, 512, 256);
            ln_fuse_kernel<2, false><<<128, 128>>>(
                ph, lp1, nullptr, ln1g + l * 512, ln1b + l * 512, ph);
            // FFN1: N=2048, gelu+bias -> bf16 split out; 256 blocks
            gemmw_kernel<1, 1><<<dim3(32, 8, 1), 256, GW_SMEM>>>(
                phh, phl, w1h, w1h, w1h, w1l, w1l, w1l,
                odummy, pfh, pfl, b1 + l * D_FF, 2048, 512, 512);
            // FFN2: K=2048 split-K4 -> 256 blocks; partials into ln2
            gemmw_kernel<4, 0><<<dim3(8, 8, 4), 256, GW_SMEM>>>(
                pfh, pfl, w2h, w2h, w2h, w2l, w2l, w2l,
                off2, nullptr, nullptr, nullptr, 512, 2048, 512);
            ln_fuse_kernel<4, true><<<128, 128>>>(
                ph, lp2, b2 + l * 512, ln2g + l * 512, ln2b + l * 512, ph);
        }
        for (int s = 0; s < N_SUB; s++) {
            refineA_kernel<<<64, 256>>>(Wemb, bemb, Wr1, br1, step, s == 0);
            refineB_kernel<<<4, 256>>>(Wr2, br2, out, step, s == 0, s == N_SUB - 1);
        }
    }
}

// round 16
// speedup vs baseline: 1.1400x; 1.0586x over previous
#include <cuda_runtime.h>
#include <cuda_bf16.h>
#include <math.h>

typedef unsigned long long u64;
typedef unsigned int u32;
#define DEV __device__ __forceinline__

constexpr int B = 4, TH = 120, STEPS = 8, D_IN = 32, D_MODEL = 512;
constexpr int N_HEADS = 8, N_LAYERS = 4, D_FF = 2048, N_SUB = 5;
constexpr int T = 128;          // TH + STEPS
constexpr int M = 512;          // B * T
constexpr float LN_EPS = 1e-5f;
constexpr float NEGMIN = -3.402823466e38f;
constexpr float EMB_SCALE = 22.627416997969522f;   // sqrt(512)
constexpr float INV_SQRT_DH = 0.125f;              // 1/sqrt(64)
constexpr int ATTN_SMEM = (128 * 68 + 32 * 132) * 4;  // 51712 bytes

// gemmw smem (bf16 elements): tile 64x64, K-chunk 64, stride-72 rows, 3 stages
constexpr int RS = 72;             // row stride (elements); (r*72*2B/16) mod 8 = r -> ldmatrix conflict-free
constexpr int AH_E = 0;            // A hi: 64 x 72
constexpr int AL_E = 4608;         // A lo
constexpr int WH_E = 9216;         // W hi: 64 x 72
constexpr int WL_E = 13824;        // W lo
constexpr int BUF_E = 18432;       // elements per stage
constexpr int NSTAGE = 3;
constexpr int GW_SMEM = BUF_E * NSTAGE * 2;  // 110592 bytes

// converted-weight offsets (elements)
constexpr int WSZ = 4 * 512 * 512;
constexpr int WSZ_FF = 4 * 2048 * 512;
constexpr int OQ = 0, OK_ = WSZ, OV = 2 * WSZ, OO = 3 * WSZ;
constexpr int O1 = 4 * WSZ, O2 = 4 * WSZ + WSZ_FF;
constexpr int WTOTAL = 4 * WSZ + 2 * WSZ_FF;

// -------- device scratch (no allocations allowed) --------
__device__ float g_buf[B][T][D_IN];
__device__ float g_h[M][D_MODEL];
__device__ float g_q[M][D_MODEL];
__device__ float g_k[M][D_MODEL];
__device__ float g_v[M][D_MODEL];
__device__ float g_part[4][M][D_MODEL];
__device__ float g_cur[B][D_IN];
__device__ float g_ffr[B][D_FF];
__device__ __nv_bfloat16 g_hh[M][D_MODEL], g_hl[M][D_MODEL];   // h split
__device__ __nv_bfloat16 g_ah[M][D_MODEL], g_al[M][D_MODEL];   // attn split
__device__ __nv_bfloat16 g_fh[M][D_FF], g_fl[M][D_FF];         // ffn1 split
__device__ __nv_bfloat16 g_wh[WTOTAL], g_wl[WTOTAL];           // weights split

// refine-kernel private grid barrier (64 blocks, all co-resident)
__device__ unsigned r_bar_count = 0;
__device__ volatile unsigned r_bar_gen = 0;

// -------- helpers --------
DEV u64 pack2(float lo, float hi) {
    u64 r; asm("mov.b64 %0, {%1, %2};" : "=l"(r) : "f"(lo), "f"(hi)); return r;
}
DEV float2 unpack2(u64 v) {
    float2 r; asm("mov.b64 {%0, %1}, %2;" : "=f"(r.x), "=f"(r.y) : "l"(v)); return r;
}
DEV void fma2(u64& c, u64 a, u64 b) {
    asm("fma.rn.f32x2 %0, %1, %2, %0;" : "+l"(c) : "l"(a), "l"(b));
}
union F4U { float4 f; u64 u[2]; };
DEV float4 ldg4(const float* p) { return __ldg((const float4*)p); }

DEV float gelu_fast(float x) {
    float w = 1.5957691216057308f * (x + 0.044715f * x * x * x);
    float t = 1.0f - 2.0f / (__expf(w) + 1.0f);
    return 0.5f * x * (1.0f + t);
}

DEV u32 smem_u32(const void* p) {
    u32 a;
    asm("{ .reg .u64 t; cvta.to.shared.u64 t, %1; cvt.u32.u64 %0, t; }"
        : "=r"(a) : "l"(p));
    return a;
}

DEV void ldsm_x4(u32* r, u32 addr) {
    asm volatile("ldmatrix.sync.aligned.m8n8.x4.shared.b16 {%0,%1,%2,%3}, [%4];"
                 : "=r"(r[0]), "=r"(r[1]), "=r"(r[2]), "=r"(r[3]) : "r"(addr));
}
DEV void mma_bf16(float* c, const u32* a, const u32* b) {
    asm volatile(
        "mma.sync.aligned.m16n8k16.row.col.f32.bf16.bf16.f32 "
        "{%0,%1,%2,%3}, {%4,%5,%6,%7}, {%8,%9}, {%0,%1,%2,%3};"
        : "+f"(c[0]), "+f"(c[1]), "+f"(c[2]), "+f"(c[3])
        : "r"(a[0]), "r"(a[1]), "r"(a[2]), "r"(a[3]), "r"(b[0]), "r"(b[1]));
}
DEV void cpasync16(u32 dst, const void* src) {
    asm volatile("cp.async.cg.shared.global [%0], [%1], 16;" :: "r"(dst), "l"(src));
}
#define CP_COMMIT() asm volatile("cp.async.commit_group;" ::: "memory")
#define CP_WAIT1() asm volatile("cp.async.wait_group 1;" ::: "memory")

DEV void rbar() {
    __syncthreads();
    if (threadIdx.x == 0) {
        unsigned gen = r_bar_gen;
        __threadfence();
        if (atomicAdd(&r_bar_count, 1u) == gridDim.x - 1) {
            r_bar_count = 0;
            __threadfence();
            r_bar_gen = gen + 1;
        } else {
            while (r_bar_gen == gen) { }
        }
    }
    __syncthreads();
}

struct O6 { float* p[6]; };
struct P4 { const float* p[4]; };

// =============== buf init ===============
__global__ void init_buf_kernel(const float* __restrict__ history) {
    int b = blockIdx.x;
    for (int idx = threadIdx.x; idx < T * D_IN; idx += blockDim.x) {
        int t = idx >> 5, i = idx & 31;
        g_buf[b][t][i] = (t < TH) ? history[(b * TH + t) * D_IN + i] : 0.0f;
    }
}

// =============== weight split conversion (once per launch) ===============
__global__ void wconv_kernel(const float* __restrict__ Wq, const float* __restrict__ Wk,
                             const float* __restrict__ Wv, const float* __restrict__ Wo,
                             const float* __restrict__ W1, const float* __restrict__ W2) {
    int seg = blockIdx.y;
    const float* src;
    __nv_bfloat16 *hi, *lo;
    int n;
    if (seg == 0)      { src = Wq; hi = g_wh + OQ;  lo = g_wl + OQ;  n = WSZ; }
    else if (seg == 1) { src = Wk; hi = g_wh + OK_; lo = g_wl + OK_; n = WSZ; }
    else if (seg == 2) { src = Wv; hi = g_wh + OV;  lo = g_wl + OV;  n = WSZ; }
    else if (seg == 3) { src = Wo; hi = g_wh + OO;  lo = g_wl + OO;  n = WSZ; }
    else if (seg == 4) { src = W1; hi = g_wh + O1;  lo = g_wl + O1;  n = WSZ_FF; }
    else               { src = W2; hi = g_wh + O2;  lo = g_wl + O2;  n = WSZ_FF; }
    int np = n >> 1;
    int stride = gridDim.x * blockDim.x;
    for (int i = blockIdx.x * blockDim.x + threadIdx.x; i < np; i += stride) {
        float2 x = ((const float2*)src)[i];
        __nv_bfloat16 h0 = __float2bfloat16(x.x), h1 = __float2bfloat16(x.y);
        __nv_bfloat162 hp; hp.x = h0; hp.y = h1;
        ((__nv_bfloat162*)hi)[i] = hp;
        __nv_bfloat162 lp;
        lp.x = __float2bfloat16(x.x - __bfloat162float(h0));
        lp.y = __float2bfloat16(x.y - __bfloat162float(h1));
        ((__nv_bfloat162*)lo)[i] = lp;
    }
}

// =============== embedding + positional encoding (+ bf16 split out) ========
__global__ void embed_kernel(const float* __restrict__ Wemb,
                             const float* __restrict__ bemb) {
    int row = blockIdx.x;
    int t = row & (T - 1);
    int b = row >> 7;
    __shared__ float xs[D_IN];
    int tid = threadIdx.x;             // 128
    if (tid < D_IN) xs[tid] = g_buf[b][t][tid];
    __syncthreads();
#pragma unroll
    for (int c = 0; c < 4; c++) {
        int d = tid + c * 128;
        const float* w = Wemb + d * D_IN;
        float s = 0.0f;
#pragma unroll
        for (int i = 0; i < 32; i += 4) {
            float4 wv = ldg4(&w[i]);
            s += wv.x * xs[i] + wv.y * xs[i + 1] + wv.z * xs[i + 2] + wv.w * xs[i + 3];
        }
        s = (s + __ldg(&bemb[d])) * EMB_SCALE;
        int j2 = d & ~1;
        float ang = (float)t * expf((float)j2 * (-9.210340371976184f / 512.0f));
        s += (d & 1) ? cosf(ang) : sinf(ang);
        g_h[row][d] = s;
        __nv_bfloat16 hh = __float2bfloat16(s);
        g_hh[row][d] = hh;
        g_hl[row][d] = __float2bfloat16(s - __bfloat162float(hh));
    }
}

// =============== warp-MMA split-bf16 GEMM, 64x64 tile, K-chunk 64, 3-stage ==
// Block 256 thr / 8 warps; warp tile 32x16 (2m x 4n warp grid).
// C = Ah*Wh + Ah*Wl + Al*Wh, fp32 accum.
// z: mat = z/NSPLIT (W select), split = z%NSPLIT (K range + out buffer).
// EPI 0: fp32 store to outs.p[z].  EPI 1: gelu(c+bias) -> bf16 hi/lo to Oh/Ol.
template <int NSPLIT, int EPI>
__global__ void __launch_bounds__(256) gemmw_kernel(
    const __nv_bfloat16* __restrict__ Ah, const __nv_bfloat16* __restrict__ Al,
    const __nv_bfloat16* __restrict__ Wh0, const __nv_bfloat16* __restrict__ Wh1,
    const __nv_bfloat16* __restrict__ Wh2,
    const __nv_bfloat16* __restrict__ Wl0, const __nv_bfloat16* __restrict__ Wl1,
    const __nv_bfloat16* __restrict__ Wl2,
    O6 outs, __nv_bfloat16* __restrict__ Oh, __nv_bfloat16* __restrict__ Ol,
    const float* __restrict__ bias, int N, int Kfull, int KS) {
    extern __shared__ __nv_bfloat16 smw[];
    u32 smb = smem_u32(smw);
    int tid = threadIdx.x, wid = tid >> 5, lid = tid & 31;
    int z = blockIdx.z;
    int mat = z / NSPLIT, split = z - mat * NSPLIT;
    const __nv_bfloat16* Wh = mat == 0 ? Wh0 : (mat == 1 ? Wh1 : Wh2);
    const __nv_bfloat16* Wl = mat == 0 ? Wl0 : (mat == 1 ? Wl1 : Wl2);
    float* O = outs.p[z];
    int koff = split * KS;
    int m0 = blockIdx.y * 64, n0 = blockIdx.x * 64;
    int mwarp = (wid & 1) * 32, nwarp = (wid >> 1) * 16;

    float c[2][2][4];
#pragma unroll
    for (int mt = 0; mt < 2; mt++)
#pragma unroll
        for (int nt = 0; nt < 2; nt++)
#pragma unroll
            for (int i = 0; i < 4; i++) c[mt][nt][i] = 0.0f;

    // staging: 2 slots/thread/array (rows r0, r0+32), 16B each
    int r0s = tid >> 3, seg = tid & 7;
    const __nv_bfloat16* pa0 = Ah + (long)(m0 + r0s) * Kfull + koff + seg * 8;
    const __nv_bfloat16* pal0 = Al + (long)(m0 + r0s) * Kfull + koff + seg * 8;
    const __nv_bfloat16* pwh0 = Wh + (long)(n0 + r0s) * Kfull + koff + seg * 8;
    const __nv_bfloat16* pwl0 = Wl + (long)(n0 + r0s) * Kfull + koff + seg * 8;
    long rj = 32l * Kfull;
    int sE0 = r0s * RS + seg * 8;
    int sE1 = sE0 + 32 * RS;

    int nch = KS / 64;
#define GW_ISSUE(ch, buf)                                                   \
    do {                                                                    \
        u32 bb = smb + 2u * ((buf) * BUF_E);                                \
        int kk2 = (ch) * 64;                                                \
        cpasync16(bb + 2u * (AH_E + sE0), pa0 + kk2);                       \
        cpasync16(bb + 2u * (AH_E + sE1), pa0 + rj + kk2);                  \
        cpasync16(bb + 2u * (AL_E + sE0), pal0 + kk2);                      \
        cpasync16(bb + 2u * (AL_E + sE1), pal0 + rj + kk2);                 \
        cpasync16(bb + 2u * (WH_E + sE0), pwh0 + kk2);                      \
        cpasync16(bb + 2u * (WH_E + sE1), pwh0 + rj + kk2);                 \
        cpasync16(bb + 2u * (WL_E + sE0), pwl0 + kk2);                      \
        cpasync16(bb + 2u * (WL_E + sE1), pwl0 + rj + kk2);                 \
    } while (0)

    GW_ISSUE(0, 0);
    CP_COMMIT();
    if (nch > 1) GW_ISSUE(1, 1);
    CP_COMMIT();

    // ldmatrix lane base offsets (elements)
    int aRowOff = (lid & 15) * RS + (lid >> 4) * 8;
    int bRowOff = ((lid & 7) + ((lid >> 4) & 1) * 8) * RS + ((lid >> 3) & 1) * 8;

    for (int ch = 0; ch < nch; ch++) {
        CP_WAIT1();
        __syncthreads();
        int lc = ch + NSTAGE - 1;
        if (lc < nch) GW_ISSUE(lc, lc % NSTAGE);
        CP_COMMIT();

        int bufE = (ch % NSTAGE) * BUF_E;
#pragma unroll
        for (int ks = 0; ks < 64; ks += 16) {
            u32 ah[2][4], al[2][4], bh[4], bl[4];
#pragma unroll
            for (int mt = 0; mt < 2; mt++) {
                int eoff = bufE + (mwarp + mt * 16) * RS + aRowOff + ks;
                ldsm_x4(ah[mt], smb + 2 * (AH_E + eoff));
                ldsm_x4(al[mt], smb + 2 * (AL_E + eoff));
            }
            {
                int eoff = bufE + nwarp * RS + bRowOff + ks;
                ldsm_x4(bh, smb + 2 * (WH_E + eoff));
                ldsm_x4(bl, smb + 2 * (WL_E + eoff));
            }
#pragma unroll
            for (int mt = 0; mt < 2; mt++)
#pragma unroll
                for (int nt = 0; nt < 2; nt++) {
                    mma_bf16(c[mt][nt], ah[mt], bh + nt * 2);
                    mma_bf16(c[mt][nt], ah[mt], bl + nt * 2);
                    mma_bf16(c[mt][nt], al[mt], bh + nt * 2);
                }
        }
    }
#undef GW_ISSUE

    // epilogue
    int r0 = m0 + mwarp + (lid >> 2);
    int cbase = n0 + nwarp + 2 * (lid & 3);
#pragma unroll
    for (int mt = 0; mt < 2; mt++) {
#pragma unroll
        for (int nt = 0; nt < 2; nt++) {
            int row = r0 + mt * 16;
            int col = cbase + nt * 8;
            float v0 = c[mt][nt][0], v1 = c[mt][nt][1];
            float v2 = c[mt][nt][2], v3 = c[mt][nt][3];
            if (EPI == 0) {
                float2 p01 = {v0, v1};
                float2 p23 = {v2, v3};
                *(float2*)&O[(long)row * N + col] = p01;
                *(float2*)&O[(long)(row + 8) * N + col] = p23;
            } else {
                float b0 = __ldg(&bias[col]), b1 = __ldg(&bias[col + 1]);
                v0 = gelu_fast(v0 + b0); v1 = gelu_fast(v1 + b1);
                v2 = gelu_fast(v2 + b0); v3 = gelu_fast(v3 + b1);
                __nv_bfloat16 h0 = __float2bfloat16(v0), h1 = __float2bfloat16(v1);
                __nv_bfloat16 h2 = __float2bfloat16(v2), h3 = __float2bfloat16(v3);
                __nv_bfloat162 hp0; hp0.x = h0; hp0.y = h1;
                __nv_bfloat162 hp1; hp1.x = h2; hp1.y = h3;
                *(__nv_bfloat162*)&Oh[(long)row * N + col] = hp0;
                *(__nv_bfloat162*)&Oh[(long)(row + 8) * N + col] = hp1;
                __nv_bfloat162 lp0, lp1;
                lp0.x = __float2bfloat16(v0 - __bfloat162float(h0));
                lp0.y = __float2bfloat16(v1 - __bfloat162float(h1));
                lp1.x = __float2bfloat16(v2 - __bfloat162float(h2));
                lp1.y = __float2bfloat16(v3 - __bfloat162float(h3));
                *(__nv_bfloat162*)&Ol[(long)row * N + col] = lp0;
                *(__nv_bfloat162*)&Ol[(long)(row + 8) * N + col] = lp1;
            }
        }
    }
}

// =============== fused LayerNorm (+ bf16 split out) =========
template <int NP, bool HB>
__global__ void ln_fuse_kernel(const float* __restrict__ X, P4 P,
                               const float* __restrict__ bias,
                               const float* __restrict__ gam,
                               const float* __restrict__ bet,
                               float* __restrict__ O) {
    int row = blockIdx.x * 4 + (threadIdx.x >> 5);
    int lane = threadIdx.x & 31;
    float4 x[4];
    float s = 0.0f;
#pragma unroll
    for (int i = 0; i < 4; i++) {
        int col = lane * 4 + i * 128;
        x[i] = ldg4(&X[row * 512 + col]);
#pragma unroll
        for (int j = 0; j < NP; j++) {
            float4 pv = ldg4(&P.p[j][row * 512 + col]);
            x[i].x += pv.x; x[i].y += pv.y; x[i].z += pv.z; x[i].w += pv.w;
        }
        if (HB) {
            float4 b4 = ldg4(&bias[col]);
            x[i].x += b4.x; x[i].y += b4.y; x[i].z += b4.z; x[i].w += b4.w;
        }
        s += x[i].x + x[i].y + x[i].z + x[i].w;
    }
#pragma unroll
    for (int o = 16; o; o >>= 1) s += __shfl_xor_sync(~0u, s, o);
    float mu = s * (1.0f / 512.0f);
    float v = 0.0f;
#pragma unroll
    for (int i = 0; i < 4; i++) {
        x[i].x -= mu; x[i].y -= mu; x[i].z -= mu; x[i].w -= mu;
        v += x[i].x * x[i].x + x[i].y * x[i].y + x[i].z * x[i].z + x[i].w * x[i].w;
    }
#pragma unroll
    for (int o = 16; o; o >>= 1) v += __shfl_xor_sync(~0u, v, o);
    float inv = 1.0f / sqrtf(v * (1.0f / 512.0f) + LN_EPS);
#pragma unroll
    for (int i = 0; i < 4; i++) {
        int col = lane * 4 + i * 128;
        float4 g4 = ldg4(&gam[col]);
        float4 b4 = ldg4(&bet[col]);
        float4 o4;
        o4.x = x[i].x * inv * g4.x + b4.x;
        o4.y = x[i].y * inv * g4.y + b4.y;
        o4.z = x[i].z * inv * g4.z + b4.z;
        o4.w = x[i].w * inv * g4.w + b4.w;
        *(float4*)&O[row * 512 + col] = o4;
        __nv_bfloat16 h0 = __float2bfloat16(o4.x), h1 = __float2bfloat16(o4.y);
        __nv_bfloat16 h2 = __float2bfloat16(o4.z), h3 = __float2bfloat16(o4.w);
        __nv_bfloat162 hp0; hp0.x = h0; hp0.y = h1;
        __nv_bfloat162 hp1; hp1.x = h2; hp1.y = h3;
        *(__nv_bfloat162*)&g_hh[row][col] = hp0;
        *(__nv_bfloat162*)&g_hh[row][col + 2] = hp1;
        __nv_bfloat162 lp0, lp1;
        lp0.x = __float2bfloat16(o4.x - __bfloat162float(h0));
        lp0.y = __float2bfloat16(o4.y - __bfloat162float(h1));
        lp1.x = __float2bfloat16(o4.z - __bfloat162float(h2));
        lp1.y = __float2bfloat16(o4.w - __bfloat162float(h3));
        *(__nv_bfloat162*)&g_hl[row][col] = lp0;
        *(__nv_bfloat162*)&g_hl[row][col + 2] = lp1;
    }
}

// =============== Attention (fp32 in, bf16 split out) =========
// mask: attend where key index > query index (anti-causal, faithful to source)
__global__ void __launch_bounds__(256) attn_kernel() {
    extern __shared__ float smf[];
    float (*Ks)[68] = (float(*)[68])smf;
    float (*Ps)[132] = (float(*)[132])(smf + 128 * 68);
    int tid = threadIdx.x;
    int qr = tid >> 3, kg = tid & 7;
    int bx = blockIdx.x;
    int b = bx >> 5, h = (bx >> 2) & 7, qt = bx & 3;
    int base = b * T, hc = h * 64;
    int qi = qt * 32 + qr;

    for (int i = tid; i < 2048; i += 256) {
        int r = i >> 4, c = i & 15;
        *(float4*)&Ks[r][c * 4] = ldg4(&g_k[base + r][hc + c * 4]);
    }
    F4U q[16];
#pragma unroll
    for (int c = 0; c < 16; c++) q[c].f = ldg4(&g_q[base + qi][hc + c * 4]);
    __syncthreads();

    float sreg[16];
    float mloc = NEGMIN;
#pragma unroll
    for (int t = 0; t < 16; t++) {
        int k = kg + 8 * t;
        u64 a0 = pack2(0.f, 0.f), a1 = a0, a2 = a0, a3 = a0;
#pragma unroll
        for (int c = 0; c < 16; c += 2) {
            F4U k0; k0.f = *(const float4*)&Ks[k][c * 4];
            F4U k1; k1.f = *(const float4*)&Ks[k][c * 4 + 4];
            fma2(a0, q[c].u[0], k0.u[0]);
            fma2(a1, q[c].u[1], k0.u[1]);
            fma2(a2, q[c + 1].u[0], k1.u[0]);
            fma2(a3, q[c + 1].u[1], k1.u[1]);
        }
        float2 p0 = unpack2(a0), p1 = unpack2(a1), p2 = unpack2(a2), p3 = unpack2(a3);
        float s = (p0.x + p0.y) + (p1.x + p1.y) + (p2.x + p2.y) + (p3.x + p3.y);
        s = (k > qi) ? s * INV_SQRT_DH : NEGMIN;
        sreg[t] = s;
        mloc = fmaxf(mloc, s);
    }
    mloc = fmaxf(mloc, __shfl_xor_sync(~0u, mloc, 1));
    mloc = fmaxf(mloc, __shfl_xor_sync(~0u, mloc, 2));
    mloc = fmaxf(mloc, __shfl_xor_sync(~0u, mloc, 4));
    float lsum = 0.0f;
#pragma unroll
    for (int t = 0; t < 16; t++) {
        float p = __expf(sreg[t] - mloc);
        Ps[qr][kg + 8 * t] = p;
        lsum += p;
    }
    lsum += __shfl_xor_sync(~0u, lsum, 1);
    lsum += __shfl_xor_sync(~0u, lsum, 2);
    lsum += __shfl_xor_sync(~0u, lsum, 4);
    float invl = 1.0f / lsum;

    __syncthreads();
    for (int i = tid; i < 2048; i += 256) {
        int r = i >> 4, c = i & 15;
        *(float4*)&Ks[r][c * 4] = ldg4(&g_v[base + r][hc + c * 4]);
    }
    __syncthreads();

    F4U o[2];
    o[0].u[0] = pack2(0.f, 0.f); o[0].u[1] = o[0].u[0];
    o[1].u[0] = o[0].u[0]; o[1].u[1] = o[0].u[0];
#pragma unroll 4
    for (int k = 0; k < 128; k++) {
        float p = Ps[qr][k];
        u64 p2 = pack2(p, p);
#pragma unroll
        for (int c = 0; c < 2; c++) {
            F4U v; v.f = *(const float4*)&Ks[k][kg * 4 + c * 32];
            fma2(o[c].u[0], p2, v.u[0]);
            fma2(o[c].u[1], p2, v.u[1]);
        }
    }
#pragma unroll
    for (int c = 0; c < 2; c++) {
        float r0 = o[c].f.x * invl, r1 = o[c].f.y * invl;
        float r2 = o[c].f.z * invl, r3 = o[c].f.w * invl;
        int colb = hc + kg * 4 + c * 32;
        __nv_bfloat16 h0 = __float2bfloat16(r0), h1 = __float2bfloat16(r1);
        __nv_bfloat16 h2 = __float2bfloat16(r2), h3 = __float2bfloat16(r3);
        __nv_bfloat162 hp0; hp0.x = h0; hp0.y = h1;
        __nv_bfloat162 hp1; hp1.x = h2; hp1.y = h3;
        *(__nv_bfloat162*)&g_ah[base + qi][colb] = hp0;
        *(__nv_bfloat162*)&g_ah[base + qi][colb + 2] = hp1;
        __nv_bfloat162 lp0, lp1;
        lp0.x = __float2bfloat16(r0 - __bfloat162float(h0));
        lp0.y = __float2bfloat16(r1 - __bfloat162float(h1));
        lp1.x = __float2bfloat16(r2 - __bfloat162float(h2));
        lp1.y = __float2bfloat16(r3 - __bfloat162float(h3));
        *(__nv_bfloat162*)&g_al[base + qi][colb] = lp0;
        *(__nv_bfloat162*)&g_al[base + qi][colb + 2] = lp1;
    }
}

// =============== fused refine: all 5 sub-steps in ONE kernel (64 blocks) ====
// A-phase: 64 blocks compute g_ffr = gelu(Wr1@comb+br1); grid barrier;
// B-phase: blocks 0..3 compute delta + update g_cur; grid barrier; repeat.
// Cross-block values (g_cur, g_ffr) read via __ldcg to avoid stale L1.
__global__ void __launch_bounds__(256) refine_kernel(
    const float* __restrict__ Wemb, const float* __restrict__ bemb,
    const float* __restrict__ Wr1, const float* __restrict__ br1,
    const float* __restrict__ Wr2, const float* __restrict__ br2,
    float* __restrict__ out, int step) {
    int b = blockIdx.x >> 4, part = blockIdx.x & 15;
    __shared__ float comb[1024];
    __shared__ float cur[32];
    __shared__ float ff[2048];
    int tid = threadIdx.x;
    int ptr = TH + step;

    for (int s = 0; s < N_SUB; s++) {
        // ---- A phase (all 64 blocks) ----
        if (tid < 32)
            cur[tid] = (s == 0) ? g_buf[b][ptr - 1][tid] : __ldcg(&g_cur[b][tid]);
        __syncthreads();
        for (int d = tid; d < 512; d += 256) {
            const float* w = &Wemb[d * 32];
            float sv = 0.0f;
#pragma unroll
            for (int i = 0; i < 32; i += 4) {
                float4 wv = ldg4(&w[i]);
                sv += wv.x * cur[i] + wv.y * cur[i + 1] + wv.z * cur[i + 2] + wv.w * cur[i + 3];
            }
            comb[d] = (sv + __ldg(&bemb[d])) * EMB_SCALE;
        }
        for (int d = tid; d < 512; d += 256) comb[512 + d] = g_h[b * T + ptr - 1][d];
        __syncthreads();

        {
            int r = part * 128 + (tid >> 1);
            int half = tid & 1;
            const float* w = &Wr1[r * 1024 + half * 512];
            const float* cb = &comb[half * 512];
            u64 a0 = pack2(0.f, 0.f), a1 = pack2(0.f, 0.f);
            for (int i = 0; i < 512; i += 4) {
                F4U wv; wv.f = ldg4(&w[i]);
                F4U cv; cv.f = *(const float4*)&cb[i];
                fma2(a0, wv.u[0], cv.u[0]);
                fma2(a1, wv.u[1], cv.u[1]);
            }
            float2 x0 = unpack2(a0), x1 = unpack2(a1);
            float sv = x0.x + x0.y + x1.x + x1.y;
            sv += __shfl_xor_sync(~0u, sv, 1);
            if (half == 0) g_ffr[b][r] = gelu_fast(sv + __ldg(&br1[r]));
        }
        rbar();

        // ---- B phase (blocks 0..3) ----
        if (blockIdx.x < 4) {
            int bb = blockIdx.x;
            for (int i = tid; i < 2048; i += 256) ff[i] = __ldcg(&g_ffr[bb][i]);
            __syncthreads();
            int i = tid >> 3, prt = tid & 7;
            const float* w = &Wr2[i * 2048 + prt * 256];
            const float* f = &ff[prt * 256];
            u64 a0 = pack2(0.f, 0.f), a1 = pack2(0.f, 0.f);
            for (int j = 0; j < 256; j += 4) {
                F4U wv; wv.f = ldg4(&w[j]);
                F4U fv; fv.f = *(const float4*)&f[j];
                fma2(a0, wv.u[0], fv.u[0]);
                fma2(a1, wv.u[1], fv.u[1]);
            }
            float2 x0 = unpack2(a0), x1 = unpack2(a1);
            float sv = x0.x + x0.y + x1.x + x1.y;
            sv += __shfl_xor_sync(~0u, sv, 1);
            sv += __shfl_xor_sync(~0u, sv, 2);
            sv += __shfl_xor_sync(~0u, sv, 4);
            if (prt == 0) {
                float basev = (s == 0) ? g_buf[bb][ptr - 1][i] : __ldcg(&g_cur[bb][i]);
                float nv = basev + sv + __ldg(&br2[i]);
                g_cur[bb][i] = nv;
                if (s == N_SUB - 1) {
                    g_buf[bb][ptr][i] = nv;
                    out[(bb * STEPS + step) * D_IN + i] = nv;
                }
            }
            __syncthreads();
        }
        rbar();
    }
}

// =============== host orchestration ===============
extern "C" void kernel_launch(void* const* d_in, const int* in_sizes, int n_in,
                              void* d_out, int out_size) {
    int o = (n_in >= 20) ? 1 : 0;   // "steps" scalar occupies index 1 if present
    const float* history = (const float*)d_in[0];
    const float* Wemb = (const float*)d_in[1 + o];
    const float* bemb = (const float*)d_in[2 + o];
    const float* Wq = (const float*)d_in[3 + o];
    const float* Wk = (const float*)d_in[4 + o];
    const float* Wv = (const float*)d_in[5 + o];
    const float* Wo = (const float*)d_in[6 + o];
    const float* ln1g = (const float*)d_in[7 + o];
    const float* ln1b = (const float*)d_in[8 + o];
    const float* W1 = (const float*)d_in[9 + o];
    const float* b1 = (const float*)d_in[10 + o];
    const float* W2 = (const float*)d_in[11 + o];
    const float* b2 = (const float*)d_in[12 + o];
    const float* ln2g = (const float*)d_in[13 + o];
    const float* ln2b = (const float*)d_in[14 + o];
    const float* Wr1 = (const float*)d_in[15 + o];
    const float* br1 = (const float*)d_in[16 + o];
    const float* Wr2 = (const float*)d_in[17 + o];
    const float* br2 = (const float*)d_in[18 + o];
    float* out = (float*)d_out;

    void* p;
    cudaGetSymbolAddress(&p, g_h);    float* ph = (float*)p;
    cudaGetSymbolAddress(&p, g_q);    float* pq = (float*)p;
    cudaGetSymbolAddress(&p, g_k);    float* pk = (float*)p;
    cudaGetSymbolAddress(&p, g_v);    float* pv = (float*)p;
    cudaGetSymbolAddress(&p, g_part); float* ppart = (float*)p;
    cudaGetSymbolAddress(&p, g_hh);   __nv_bfloat16* phh = (__nv_bfloat16*)p;
    cudaGetSymbolAddress(&p, g_hl);   __nv_bfloat16* phl = (__nv_bfloat16*)p;
    cudaGetSymbolAddress(&p, g_ah);   __nv_bfloat16* pah = (__nv_bfloat16*)p;
    cudaGetSymbolAddress(&p, g_al);   __nv_bfloat16* pal = (__nv_bfloat16*)p;
    cudaGetSymbolAddress(&p, g_fh);   __nv_bfloat16* pfh = (__nv_bfloat16*)p;
    cudaGetSymbolAddress(&p, g_fl);   __nv_bfloat16* pfl = (__nv_bfloat16*)p;
    cudaGetSymbolAddress(&p, g_wh);   __nv_bfloat16* pwh = (__nv_bfloat16*)p;
    cudaGetSymbolAddress(&p, g_wl);   __nv_bfloat16* pwl = (__nv_bfloat16*)p;
    float* pp0 = ppart;
    float* pp1 = ppart + M * D_MODEL;
    float* pp2 = ppart + 2 * M * D_MODEL;
    float* pp3 = ppart + 3 * M * D_MODEL;

    cudaFuncSetAttribute(attn_kernel, cudaFuncAttributeMaxDynamicSharedMemorySize,
                         ATTN_SMEM);
    cudaFuncSetAttribute(gemmw_kernel<1, 0>,
                         cudaFuncAttributeMaxDynamicSharedMemorySize, GW_SMEM);
    cudaFuncSetAttribute(gemmw_kernel<2, 0>,
                         cudaFuncAttributeMaxDynamicSharedMemorySize, GW_SMEM);
    cudaFuncSetAttribute(gemmw_kernel<1, 1>,
                         cudaFuncAttributeMaxDynamicSharedMemorySize, GW_SMEM);
    cudaFuncSetAttribute(gemmw_kernel<4, 0>,
                         cudaFuncAttributeMaxDynamicSharedMemorySize, GW_SMEM);

    O6 oqkv = {{pq, pk, pv, nullptr, nullptr, nullptr}};
    O6 owo = {{pp0, pp1, nullptr, nullptr, nullptr, nullptr}};
    O6 odummy = {{nullptr, nullptr, nullptr, nullptr, nullptr, nullptr}};
    O6 off2 = {{pp0, pp1, pp2, pp3, nullptr, nullptr}};
    P4 lp1 = {{pp0, pp1, nullptr, nullptr}};
    P4 lp2 = {{pp0, pp1, pp2, pp3}};

    init_buf_kernel<<<B, 256>>>(history);
    wconv_kernel<<<dim3(512, 6), 256>>>(Wq, Wk, Wv, Wo, W1, W2);

    for (int step = 0; step < STEPS; step++) {
        embed_kernel<<<M, 128>>>(Wemb, bemb);
        for (int l = 0; l < N_LAYERS; l++) {
            const __nv_bfloat16* wqh = pwh + OQ + l * 512 * 512;
            const __nv_bfloat16* wkh = pwh + OK_ + l * 512 * 512;
            const __nv_bfloat16* wvh = pwh + OV + l * 512 * 512;
            const __nv_bfloat16* woh = pwh + OO + l * 512 * 512;
            const __nv_bfloat16* w1h = pwh + O1 + l * 2048 * 512;
            const __nv_bfloat16* w2h = pwh + O2 + l * 512 * 2048;
            const __nv_bfloat16* wql = pwl + OQ + l * 512 * 512;
            const __nv_bfloat16* wkl = pwl + OK_ + l * 512 * 512;
            const __nv_bfloat16* wvl = pwl + OV + l * 512 * 512;
            const __nv_bfloat16* wol = pwl + OO + l * 512 * 512;
            const __nv_bfloat16* w1l = pwl + O1 + l * 2048 * 512;
            const __nv_bfloat16* w2l = pwl + O2 + l * 512 * 2048;

            // QKV: 3 mats, full K -> 192 blocks (64x64 tiles)
            gemmw_kernel<1, 0><<<dim3(8, 8, 3), 256, GW_SMEM>>>(
                phh, phl, wqh, wkh, wvh, wql, wkl, wvl,
                oqkv, nullptr, nullptr, nullptr, 512, 512, 512);
            attn_kernel<<<128, 256, ATTN_SMEM>>>();
            // Wo: split-K2 -> 128 blocks; partials into ln1
            gemmw_kernel<2, 0><<<dim3(8, 8, 2), 256, GW_SMEM>>>(
                pah, pal, woh, woh, woh, wol, wol, wol,
                owo, nullptr, nullptr, nullptr, 512, 512, 256);
            ln_fuse_kernel<2, false><<<128, 128>>>(
                ph, lp1, nullptr, ln1g + l * 512, ln1b + l * 512, ph);
            // FFN1: N=2048, gelu+bias -> bf16 split out; 256 blocks
            gemmw_kernel<1, 1><<<dim3(32, 8, 1), 256, GW_SMEM>>>(
                phh, phl, w1h, w1h, w1h, w1l, w1l, w1l,
                odummy, pfh, pfl, b1 + l * D_FF, 2048, 512, 512);
            // FFN2: K=2048 split-K4 -> 256 blocks; partials into ln2
            gemmw_kernel<4, 0><<<dim3(8, 8, 4), 256, GW_SMEM>>>(
                pfh, pfl, w2h, w2h, w2h, w2l, w2l, w2l,
                off2, nullptr, nullptr, nullptr, 512, 2048, 512);
            ln_fuse_kernel<4, true><<<128, 128>>>(
                ph, lp2, b2 + l * 512, ln2g + l * 512, ln2b + l * 512, ph);
        }
        refine_kernel<<<64, 256>>>(Wemb, bemb, Wr1, br1, Wr2, br2, out, step);
    }
}